// round 12
// baseline (speedup 1.0000x reference)
#include <cuda_runtime.h>
#include <cuda_fp16.h>
#include <cstdint>

#define NPTS  60000
#define KNBR  27
#define CDIM  128
#define EPSBN 1e-5f
#define SLOPE 0.01f

// ---------------- device globals (no allocations allowed) ----------------
__device__ __align__(16) __half g_x16[(size_t)NPTS * CDIM];     // fp16 input (x, then y1)
__device__ __align__(16) __half g_wt1[KNBR * CDIM * CDIM];      // W1^T fp16: [k][n][c]
__device__ __align__(16) __half g_wt2[KNBR * CDIM * CDIM];
__device__ float         g_h1[(size_t)NPTS * CDIM];             // conv output scratch
__device__ __align__(16) unsigned char g_zero[256];
__device__ float         g_sums[512];
__device__ float         g_bn[512];
__device__ unsigned      g_flags;
__device__ unsigned      g_done;
__device__ int           g_mask_mode;

// ---------------- prep: x -> fp16, zero session state (R10-fixed) ----------------
__global__ void prep_pack_kernel(const float* __restrict__ x) {
    long i = (long)blockIdx.x * blockDim.x + threadIdx.x;
    if (i < (long)NPTS * CDIM) g_x16[i] = __float2half_rn(x[i]);
    if (blockIdx.x == 0) {
        int t = threadIdx.x;                 // blockDim = 256
        g_sums[t]       = 0.f;
        g_sums[t + 256] = 0.f;
        g_zero[t] = 0;
        if (t == 0) { g_flags = 0u; g_done = 0u; }
    }
}
__global__ void prep_w_kernel(const float* __restrict__ W1, const float* __restrict__ W2) {
    int i = blockIdx.x * blockDim.x + threadIdx.x;
    if (i < KNBR * CDIM * CDIM) {
        int k = i >> 14, rem = i & 16383, n = rem >> 7, c = rem & 127;
        int src = (k << 14) + (c << 7) + n;
        g_wt1[i] = __float2half_rn(W1[src]);
        g_wt2[i] = __float2half_rn(W2[src]);
    }
}

// ---------------- fused mask-dtype detect + resolve ----------------
__global__ void detect_resolve_kernel(const unsigned* __restrict__ w, int nwords) {
    unsigned f = 0u;
    for (int i = blockIdx.x * blockDim.x + threadIdx.x; i < nwords;
         i += gridDim.x * blockDim.x) {
        unsigned v = w[i];
        if (v == 0x3F800000u)                          f |= 1u;
        else if (v == 0x3F803F80u || v == 0x00003F80u) f |= 2u;
        else if (v > 1u)                               f |= 4u;
    }
    f = __reduce_or_sync(0xFFFFFFFFu, f);
    if ((threadIdx.x & 31) == 0 && f) atomicOr(&g_flags, f);
    __threadfence();
    __syncthreads();
    if (threadIdx.x == 0) {
        unsigned tick = atomicAdd(&g_done, 1u);
        if (tick == gridDim.x - 1) {
            __threadfence();
            unsigned ff = g_flags;
            g_mask_mode = (ff & 2u) ? 3 : (ff & 1u) ? 0 : (ff & 4u) ? 2 : 1;
            g_done = 0u;
        }
    }
}
__device__ __forceinline__ float load_mask(const void* m, long i, int mode) {
    switch (mode) {
        case 0:  return ((const float*)m)[i];
        case 1:  return (float)(((const int*)m)[i] != 0);
        case 2:  return (float)(((const unsigned char*)m)[i] != 0);
        default: return (((const unsigned short*)m)[i] != 0) ? 1.f : 0.f;
    }
}

// ---------------- fp16 mma.sync gather-GEMM, 128x64 CTA tile, 2 CTAs/SM ----------------
#define NSTG     3
#define STGB     24576           // per stage: A 16K | B 8K
#define OFF_B    16384
#define OFF_NBR  73728           // 128*27*4 = 13824
#define OFF_MSK  87552           // 128*27*4 (floats)
#define SMEM_DYN (101376 + 1024)
#define NSTAGES_TOTAL (2 * KNBR) // 54

__device__ __forceinline__ uint32_t sw128(uint32_t off) { return off ^ ((off >> 3) & 0x70); }
__device__ __forceinline__ void cp16(uint32_t dst, const void* src) {
    asm volatile("cp.async.cg.shared.global [%0], [%1], 16;" :: "r"(dst), "l"(src) : "memory");
}
#define CP_COMMIT() asm volatile("cp.async.commit_group;" ::: "memory")
#define CP_WAIT2()  asm volatile("cp.async.wait_group 2;" ::: "memory")

__device__ __forceinline__ void ldsm4(uint32_t* r, uint32_t addr) {
    asm volatile("ldmatrix.sync.aligned.m8n8.x4.shared.b16 {%0,%1,%2,%3}, [%4];"
                 : "=r"(r[0]), "=r"(r[1]), "=r"(r[2]), "=r"(r[3]) : "r"(addr));
}
__device__ __forceinline__ void mma16816(float* c, const uint32_t* a, const uint32_t* b) {
    asm volatile(
        "mma.sync.aligned.m16n8k16.row.col.f32.f16.f16.f32 "
        "{%0,%1,%2,%3}, {%4,%5,%6,%7}, {%8,%9}, {%0,%1,%2,%3};"
        : "+f"(c[0]), "+f"(c[1]), "+f"(c[2]), "+f"(c[3])
        : "r"(a[0]), "r"(a[1]), "r"(a[2]), "r"(a[3]), "r"(b[0]), "r"(b[1]));
}

__global__ __launch_bounds__(256, 2)
void conv_mma_kernel(const __half* __restrict__ X16, const __half* __restrict__ Wt,
                     const int* __restrict__ nbr, const void* __restrict__ mask,
                     const unsigned char* __restrict__ zpage, float* __restrict__ out)
{
    extern __shared__ char smem_raw[];
    uint32_t sb   = (uint32_t)__cvta_generic_to_shared(smem_raw);
    uint32_t base = (sb + 1023) & ~1023u;
    char* smem    = smem_raw + (base - sb);

    int*   s_nbr = (int*)(smem + OFF_NBR);
    float* s_msk = (float*)(smem + OFF_MSK);

    const int tid = threadIdx.x, lane = tid & 31, wid = tid >> 5;
    const int m0 = (blockIdx.x >> 1) * 128;       // row tile
    const int n0 = (blockIdx.x & 1) * 64;         // col half
    const int mode = g_mask_mode;

    for (int i = tid; i < 128 * KNBR; i += 256) {
        int r = i / KNBR, kk = i - r * KNBR, m = m0 + r;
        if (m < NPTS) {
            long idx = (long)m * KNBR + kk;
            s_nbr[i] = nbr[idx];
            s_msk[i] = load_mask(mask, idx, mode);
        } else { s_nbr[i] = 0; s_msk[i] = 0.f; }
    }
    __syncthreads();

    float acc[2][4][4];
    #pragma unroll
    for (int mt = 0; mt < 2; ++mt)
        #pragma unroll
        for (int n = 0; n < 4; ++n)
            #pragma unroll
            for (int j = 0; j < 4; ++j) acc[mt][n][j] = 0.f;

    const int wm = (wid & 3) * 32;    // warp M offset (4 warps over 128 rows)
    const int wn = (wid >> 2) * 32;   // warp N offset (2 warps over 64 cols)

    // stage s: neighbor k=s>>1, channels cc=(s&1)*64
    auto load_stage = [&](int s) {
        const int k = s >> 1, cc = (s & 1) << 6;
        const uint32_t stb = base + (uint32_t)(s % NSTG) * STGB;
        // A: 128 rows x 8 chunks = 1024 cp16 (4/thread)
        #pragma unroll
        for (int j = 0; j < 4; ++j) {
            const int idx = tid * 4 + j;
            const int row = idx >> 3, ch = idx & 7;
            const uint32_t woff = sw128((uint32_t)row * 128 + ch * 16);
            const int nb = s_nbr[row * KNBR + k];
            const bool mk = s_msk[row * KNBR + k] != 0.f;
            const size_t eoff = (size_t)nb * CDIM + cc + ch * 8;
            cp16(stb + woff, mk ? (const void*)(X16 + eoff) : (const void*)zpage);
        }
        // B: 64 rows x 8 chunks = 512 cp16 (2/thread)
        #pragma unroll
        for (int j = 0; j < 2; ++j) {
            const int idx = tid * 2 + j;
            const int row = idx >> 3, ch = idx & 7;
            const uint32_t woff = sw128((uint32_t)row * 128 + ch * 16);
            const size_t boff = ((size_t)k * CDIM + n0 + row) * CDIM + cc + ch * 8;
            cp16(stb + OFF_B + woff, Wt + boff);
        }
    };

    load_stage(0); CP_COMMIT();
    load_stage(1); CP_COMMIT();

    for (int s = 0; s < NSTAGES_TOTAL; ++s) {
        if (s + 2 < NSTAGES_TOTAL) load_stage(s + 2);
        CP_COMMIT();
        CP_WAIT2();                 // stage s arrived (<=2 younger pending)
        __syncthreads();
        const uint32_t stb = base + (uint32_t)(s % NSTG) * STGB;

        #pragma unroll
        for (int kk = 0; kk < 4; ++kk) {
            uint32_t aF[2][4];
            #pragma unroll
            for (int mt = 0; mt < 2; ++mt) {
                const int row  = wm + mt * 16 + (lane & 7) + ((lane >> 3) & 1) * 8;
                const int colb = kk * 32 + ((lane >> 4) & 1) * 16;
                ldsm4(aF[mt], stb + sw128((uint32_t)row * 128 + colb));
            }
            uint32_t bF[4][2];
            #pragma unroll
            for (int nt = 0; nt < 2; ++nt) {
                const int nrow = wn + nt * 16 + ((lane >> 4) & 1) * 8 + (lane & 7);
                const int colb = kk * 32 + ((lane >> 3) & 1) * 16;
                uint32_t t[4];
                ldsm4(t, stb + OFF_B + sw128((uint32_t)nrow * 128 + colb));
                bF[nt*2][0] = t[0]; bF[nt*2][1] = t[1];
                bF[nt*2+1][0] = t[2]; bF[nt*2+1][1] = t[3];
            }
            #pragma unroll
            for (int mt = 0; mt < 2; ++mt)
                #pragma unroll
                for (int n = 0; n < 4; ++n)
                    mma16816(acc[mt][n], aF[mt], bF[n]);
        }
        __syncthreads();           // release buffer (s%NSTG) before reload
    }

    // epilogue: fp32 accumulators -> gmem
    #pragma unroll
    for (int mt = 0; mt < 2; ++mt) {
        const int row = m0 + wm + mt * 16 + (lane >> 2);
        #pragma unroll
        for (int n = 0; n < 4; ++n) {
            const int col = n0 + wn + n * 8 + (lane & 3) * 2;
            if (row < NPTS)
                *(float2*)(out + (size_t)row * CDIM + col) = make_float2(acc[mt][n][0], acc[mt][n][1]);
            if (row + 8 < NPTS)
                *(float2*)(out + (size_t)(row + 8) * CDIM + col) = make_float2(acc[mt][n][2], acc[mt][n][3]);
        }
    }
}

// ---------------- BN stats / finalize / fused elementwise ----------------
__global__ void stats_kernel(const float* __restrict__ h, int off) {
    int c    = threadIdx.x;
    int row0 = blockIdx.x * 512;
    int rend = min(row0 + 512, NPTS);
    float s = 0.f, sq = 0.f;
    for (int r = row0; r < rend; ++r) {
        float v = h[(size_t)r * CDIM + c];
        s += v; sq += v * v;
    }
    atomicAdd(&g_sums[off + c], s);
    atomicAdd(&g_sums[off + 128 + c], sq);
}
__global__ void finalize_kernel(const float* __restrict__ gamma,
                                const float* __restrict__ beta, int off) {
    int c = threadIdx.x;
    const float invN = 1.f / (float)NPTS;
    float mean = g_sums[off + c] * invN;
    float var  = g_sums[off + 128 + c] * invN - mean * mean;
    float sc   = gamma[c] / sqrtf(var + EPSBN);
    g_bn[off + c]       = sc;
    g_bn[off + 128 + c] = beta[c] - mean * sc;
}
// y1 = lrelu(bn1(h1)) -> fp16 for conv2
__global__ void bn_lrelu_pack_kernel(const float* __restrict__ h) {
    int i = blockIdx.x * blockDim.x + threadIdx.x;
    if (i < NPTS * CDIM) {
        int c = i & 127;
        float v = fmaf(h[i], g_bn[c], g_bn[128 + c]);
        v = v > 0.f ? v : SLOPE * v;
        g_x16[i] = __float2half_rn(v);
    }
}
// out = lrelu(bn2(h2) + x) in place
__global__ void bn_res_lrelu_kernel(float* __restrict__ h2, const float* __restrict__ x) {
    int i = blockIdx.x * blockDim.x + threadIdx.x;
    if (i < NPTS * CDIM) {
        int c = i & 127;
        float v = fmaf(h2[i], g_bn[256 + c], g_bn[384 + c]) + x[i];
        h2[i] = v > 0.f ? v : SLOPE * v;
    }
}

// ---------------- launch ----------------
extern "C" void kernel_launch(void* const* d_in, const int* in_sizes, int n_in,
                              void* d_out, int out_size)
{
    const float* x    = (const float*)d_in[0];
    const int*   nbr  = (const int*)d_in[1];
    const void*  mask = d_in[2];
    const float* W1   = (const float*)d_in[3];
    const float* W2   = (const float*)d_in[4];
    const float* g1   = (const float*)d_in[5];
    const float* b1   = (const float*)d_in[6];
    const float* g2   = (const float*)d_in[7];
    const float* b2   = (const float*)d_in[8];
    float* out = (float*)d_out;

    float* h1 = nullptr;  cudaGetSymbolAddress((void**)&h1, g_h1);
    __half *x16, *wt1, *wt2;
    cudaGetSymbolAddress((void**)&x16, g_x16);
    cudaGetSymbolAddress((void**)&wt1, g_wt1);
    cudaGetSymbolAddress((void**)&wt2, g_wt2);
    unsigned char* zp = nullptr;
    cudaGetSymbolAddress((void**)&zp, g_zero);

    cudaFuncSetAttribute(conv_mma_kernel,
                         cudaFuncAttributeMaxDynamicSharedMemorySize, SMEM_DYN);

    const int conv_blocks = 2 * ((NPTS + 127) / 128);    // 938 (128x64 tiles)
    const int ew_blocks   = (NPTS * CDIM + 255) / 256;   // 30000
    const int st_blocks   = (NPTS + 511) / 512;          // 118
    const int w_blocks    = (KNBR * CDIM * CDIM + 255) / 256;
    const int mask_words  = (NPTS * KNBR) / 4;           // 405000

    prep_pack_kernel<<<ew_blocks, 256>>>(x);                                   // 0
    prep_w_kernel<<<w_blocks, 256>>>(W1, W2);                                  // 1
    detect_resolve_kernel<<<480, 256>>>((const unsigned*)mask, mask_words);    // 2

    conv_mma_kernel<<<conv_blocks, 256, SMEM_DYN>>>(x16, wt1, nbr, mask, zp, h1);  // 3 (profiled)
    stats_kernel<<<st_blocks, 128>>>(h1, 0);                                   // 4
    finalize_kernel<<<1, 128>>>(g1, b1, 0);                                    // 5
    bn_lrelu_pack_kernel<<<ew_blocks, 256>>>(h1);                              // 6

    conv_mma_kernel<<<conv_blocks, 256, SMEM_DYN>>>(x16, wt2, nbr, mask, zp, out); // 7
    stats_kernel<<<st_blocks, 128>>>(out, 256);                                // 8
    finalize_kernel<<<1, 128>>>(g2, b2, 256);                                  // 9
    bn_res_lrelu_kernel<<<ew_blocks, 256>>>(out, x);                           // 10
}

// round 13
// speedup vs baseline: 9.9155x; 9.9155x over previous
#include <cuda_runtime.h>
#include <cuda_fp16.h>
#include <cstdint>

#define NPTS  60000
#define KNBR  27
#define CDIM  128
#define EPSBN 1e-5f
#define SLOPE 0.01f

// ---------------- device globals (no allocations allowed) ----------------
__device__ __align__(16) __half g_x16[(size_t)NPTS * CDIM];     // fp16 input (x, then y1)
__device__ __align__(16) __half g_wt1[KNBR * CDIM * CDIM];      // W1^T fp16: [k][n][c]
__device__ __align__(16) __half g_wt2[KNBR * CDIM * CDIM];
__device__ float         g_h1[(size_t)NPTS * CDIM];             // conv output scratch
__device__ float         g_sums[512];
__device__ float         g_bn[512];
__device__ unsigned      g_flags;
__device__ unsigned      g_done;
__device__ int           g_mask_mode;

// ---------------- prep: x -> fp16, zero session state ----------------
__global__ void prep_pack_kernel(const float* __restrict__ x) {
    long i = (long)blockIdx.x * blockDim.x + threadIdx.x;
    if (i < (long)NPTS * CDIM) g_x16[i] = __float2half_rn(x[i]);
    if (blockIdx.x == 0) {
        int t = threadIdx.x;                 // blockDim = 256
        g_sums[t]       = 0.f;
        g_sums[t + 256] = 0.f;
        if (t == 0) { g_flags = 0u; g_done = 0u; }
    }
}
__global__ void prep_w_kernel(const float* __restrict__ W1, const float* __restrict__ W2) {
    int i = blockIdx.x * blockDim.x + threadIdx.x;
    if (i < KNBR * CDIM * CDIM) {
        int k = i >> 14, rem = i & 16383, n = rem >> 7, c = rem & 127;
        int src = (k << 14) + (c << 7) + n;
        g_wt1[i] = __float2half_rn(W1[src]);
        g_wt2[i] = __float2half_rn(W2[src]);
    }
}

// ---------------- fused mask-dtype detect + resolve ----------------
__global__ void detect_resolve_kernel(const unsigned* __restrict__ w, int nwords) {
    unsigned f = 0u;
    for (int i = blockIdx.x * blockDim.x + threadIdx.x; i < nwords;
         i += gridDim.x * blockDim.x) {
        unsigned v = w[i];
        if (v == 0x3F800000u)                          f |= 1u;
        else if (v == 0x3F803F80u || v == 0x00003F80u) f |= 2u;
        else if (v > 1u)                               f |= 4u;
    }
    f = __reduce_or_sync(0xFFFFFFFFu, f);
    if ((threadIdx.x & 31) == 0 && f) atomicOr(&g_flags, f);
    __threadfence();
    __syncthreads();
    if (threadIdx.x == 0) {
        unsigned tick = atomicAdd(&g_done, 1u);
        if (tick == gridDim.x - 1) {
            __threadfence();
            unsigned ff = g_flags;
            g_mask_mode = (ff & 2u) ? 3 : (ff & 1u) ? 0 : (ff & 4u) ? 2 : 1;
            g_done = 0u;
        }
    }
}
__device__ __forceinline__ float load_mask(const void* m, long i, int mode) {
    switch (mode) {
        case 0:  return ((const float*)m)[i];
        case 1:  return (float)(((const int*)m)[i] != 0);
        case 2:  return (float)(((const unsigned char*)m)[i] != 0);
        default: return (((const unsigned short*)m)[i] != 0) ? 1.f : 0.f;
    }
}

// ---------------- fp16 mma.sync gather-GEMM, 128x64 CTA tile, 2 CTAs/SM ----------------
#define NSTG     3
#define STGB     24576           // per stage: A 16K | B 8K
#define OFF_B    16384
#define OFF_NBR  73728           // 128*27*4 = 13824
#define OFF_MSK  87552           // 128*27*4 (floats)
#define SMEM_DYN (101376 + 1024)
#define NSTAGES_TOTAL (2 * KNBR) // 54

__device__ __forceinline__ uint32_t sw128(uint32_t off) { return off ^ ((off >> 3) & 0x70); }
// cp.async with zfill: src_size=0 -> hardware writes zeros, NO global read (kills the
// zero-page hot-line that serialized one L2 slice in R4/R10/R12).
__device__ __forceinline__ void cp16z(uint32_t dst, const void* src, uint32_t ssize) {
    asm volatile("cp.async.cg.shared.global [%0], [%1], 16, %2;"
                 :: "r"(dst), "l"(src), "r"(ssize) : "memory");
}
__device__ __forceinline__ void cp16(uint32_t dst, const void* src) {
    asm volatile("cp.async.cg.shared.global [%0], [%1], 16;" :: "r"(dst), "l"(src) : "memory");
}
#define CP_COMMIT() asm volatile("cp.async.commit_group;" ::: "memory")
#define CP_WAIT2()  asm volatile("cp.async.wait_group 2;" ::: "memory")

__device__ __forceinline__ void ldsm4(uint32_t* r, uint32_t addr) {
    asm volatile("ldmatrix.sync.aligned.m8n8.x4.shared.b16 {%0,%1,%2,%3}, [%4];"
                 : "=r"(r[0]), "=r"(r[1]), "=r"(r[2]), "=r"(r[3]) : "r"(addr));
}
__device__ __forceinline__ void mma16816(float* c, const uint32_t* a, const uint32_t* b) {
    asm volatile(
        "mma.sync.aligned.m16n8k16.row.col.f32.f16.f16.f32 "
        "{%0,%1,%2,%3}, {%4,%5,%6,%7}, {%8,%9}, {%0,%1,%2,%3};"
        : "+f"(c[0]), "+f"(c[1]), "+f"(c[2]), "+f"(c[3])
        : "r"(a[0]), "r"(a[1]), "r"(a[2]), "r"(a[3]), "r"(b[0]), "r"(b[1]));
}

__global__ __launch_bounds__(256, 2)
void conv_mma_kernel(const __half* __restrict__ X16, const __half* __restrict__ Wt,
                     const int* __restrict__ nbr, const void* __restrict__ mask,
                     float* __restrict__ out)
{
    extern __shared__ char smem_raw[];
    uint32_t sb   = (uint32_t)__cvta_generic_to_shared(smem_raw);
    uint32_t base = (sb + 1023) & ~1023u;
    char* smem    = smem_raw + (base - sb);

    int*   s_nbr = (int*)(smem + OFF_NBR);
    float* s_msk = (float*)(smem + OFF_MSK);

    const int tid = threadIdx.x, lane = tid & 31, wid = tid >> 5;
    const int m0 = (blockIdx.x >> 1) * 128;       // row tile
    const int n0 = (blockIdx.x & 1) * 64;         // col half
    const int mode = g_mask_mode;

    for (int i = tid; i < 128 * KNBR; i += 256) {
        int r = i / KNBR, kk = i - r * KNBR, m = m0 + r;
        if (m < NPTS) {
            long idx = (long)m * KNBR + kk;
            s_nbr[i] = nbr[idx];
            s_msk[i] = load_mask(mask, idx, mode);
        } else { s_nbr[i] = 0; s_msk[i] = 0.f; }
    }
    __syncthreads();

    float acc[2][4][4];
    #pragma unroll
    for (int mt = 0; mt < 2; ++mt)
        #pragma unroll
        for (int n = 0; n < 4; ++n)
            #pragma unroll
            for (int j = 0; j < 4; ++j) acc[mt][n][j] = 0.f;

    const int wm = (wid & 3) * 32;    // warp M offset (4 warps over 128 rows)
    const int wn = (wid >> 2) * 32;   // warp N offset (2 warps over 64 cols)

    // stage s: neighbor k=s>>1, channels cc=(s&1)*64
    auto load_stage = [&](int s) {
        const int k = s >> 1, cc = (s & 1) << 6;
        const uint32_t stb = base + (uint32_t)(s % NSTG) * STGB;
        // A: 128 rows x 8 chunks = 1024 cp16 (4/thread); masked rows zfill
        #pragma unroll
        for (int j = 0; j < 4; ++j) {
            const int idx = tid * 4 + j;
            const int row = idx >> 3, ch = idx & 7;
            const uint32_t woff = sw128((uint32_t)row * 128 + ch * 16);
            const int nb = s_nbr[row * KNBR + k];
            const uint32_t ssize = (s_msk[row * KNBR + k] != 0.f) ? 16u : 0u;
            const size_t eoff = (size_t)nb * CDIM + cc + ch * 8;
            cp16z(stb + woff, X16 + eoff, ssize);
        }
        // B: 64 rows x 8 chunks = 512 cp16 (2/thread)
        #pragma unroll
        for (int j = 0; j < 2; ++j) {
            const int idx = tid * 2 + j;
            const int row = idx >> 3, ch = idx & 7;
            const uint32_t woff = sw128((uint32_t)row * 128 + ch * 16);
            const size_t boff = ((size_t)k * CDIM + n0 + row) * CDIM + cc + ch * 8;
            cp16(stb + OFF_B + woff, Wt + boff);
        }
    };

    load_stage(0); CP_COMMIT();
    load_stage(1); CP_COMMIT();

    for (int s = 0; s < NSTAGES_TOTAL; ++s) {
        if (s + 2 < NSTAGES_TOTAL) load_stage(s + 2);
        CP_COMMIT();
        CP_WAIT2();                 // stage s arrived (<=2 younger pending)
        __syncthreads();
        const uint32_t stb = base + (uint32_t)(s % NSTG) * STGB;

        #pragma unroll
        for (int kk = 0; kk < 4; ++kk) {
            uint32_t aF[2][4];
            #pragma unroll
            for (int mt = 0; mt < 2; ++mt) {
                const int row  = wm + mt * 16 + (lane & 7) + ((lane >> 3) & 1) * 8;
                const int colb = kk * 32 + ((lane >> 4) & 1) * 16;
                ldsm4(aF[mt], stb + sw128((uint32_t)row * 128 + colb));
            }
            uint32_t bF[4][2];
            #pragma unroll
            for (int nt = 0; nt < 2; ++nt) {
                const int nrow = wn + nt * 16 + ((lane >> 4) & 1) * 8 + (lane & 7);
                const int colb = kk * 32 + ((lane >> 3) & 1) * 16;
                uint32_t t[4];
                ldsm4(t, stb + OFF_B + sw128((uint32_t)nrow * 128 + colb));
                bF[nt*2][0] = t[0]; bF[nt*2][1] = t[1];
                bF[nt*2+1][0] = t[2]; bF[nt*2+1][1] = t[3];
            }
            #pragma unroll
            for (int mt = 0; mt < 2; ++mt)
                #pragma unroll
                for (int n = 0; n < 4; ++n)
                    mma16816(acc[mt][n], aF[mt], bF[n]);
        }
        __syncthreads();           // release buffer (s%NSTG) before reload
    }

    // epilogue: fp32 accumulators -> gmem
    #pragma unroll
    for (int mt = 0; mt < 2; ++mt) {
        const int row = m0 + wm + mt * 16 + (lane >> 2);
        #pragma unroll
        for (int n = 0; n < 4; ++n) {
            const int col = n0 + wn + n * 8 + (lane & 3) * 2;
            if (row < NPTS)
                *(float2*)(out + (size_t)row * CDIM + col) = make_float2(acc[mt][n][0], acc[mt][n][1]);
            if (row + 8 < NPTS)
                *(float2*)(out + (size_t)(row + 8) * CDIM + col) = make_float2(acc[mt][n][2], acc[mt][n][3]);
        }
    }
}

// ---------------- BN stats / finalize / fused elementwise ----------------
__global__ void stats_kernel(const float* __restrict__ h, int off) {
    int c    = threadIdx.x;
    int row0 = blockIdx.x * 512;
    int rend = min(row0 + 512, NPTS);
    float s = 0.f, sq = 0.f;
    for (int r = row0; r < rend; ++r) {
        float v = h[(size_t)r * CDIM + c];
        s += v; sq += v * v;
    }
    atomicAdd(&g_sums[off + c], s);
    atomicAdd(&g_sums[off + 128 + c], sq);
}
__global__ void finalize_kernel(const float* __restrict__ gamma,
                                const float* __restrict__ beta, int off) {
    int c = threadIdx.x;
    const float invN = 1.f / (float)NPTS;
    float mean = g_sums[off + c] * invN;
    float var  = g_sums[off + 128 + c] * invN - mean * mean;
    float sc   = gamma[c] / sqrtf(var + EPSBN);
    g_bn[off + c]       = sc;
    g_bn[off + 128 + c] = beta[c] - mean * sc;
}
// y1 = lrelu(bn1(h1)) -> fp16 for conv2
__global__ void bn_lrelu_pack_kernel(const float* __restrict__ h) {
    int i = blockIdx.x * blockDim.x + threadIdx.x;
    if (i < NPTS * CDIM) {
        int c = i & 127;
        float v = fmaf(h[i], g_bn[c], g_bn[128 + c]);
        v = v > 0.f ? v : SLOPE * v;
        g_x16[i] = __float2half_rn(v);
    }
}
// out = lrelu(bn2(h2) + x) in place
__global__ void bn_res_lrelu_kernel(float* __restrict__ h2, const float* __restrict__ x) {
    int i = blockIdx.x * blockDim.x + threadIdx.x;
    if (i < NPTS * CDIM) {
        int c = i & 127;
        float v = fmaf(h2[i], g_bn[256 + c], g_bn[384 + c]) + x[i];
        h2[i] = v > 0.f ? v : SLOPE * v;
    }
}

// ---------------- launch ----------------
extern "C" void kernel_launch(void* const* d_in, const int* in_sizes, int n_in,
                              void* d_out, int out_size)
{
    const float* x    = (const float*)d_in[0];
    const int*   nbr  = (const int*)d_in[1];
    const void*  mask = d_in[2];
    const float* W1   = (const float*)d_in[3];
    const float* W2   = (const float*)d_in[4];
    const float* g1   = (const float*)d_in[5];
    const float* b1   = (const float*)d_in[6];
    const float* g2   = (const float*)d_in[7];
    const float* b2   = (const float*)d_in[8];
    float* out = (float*)d_out;

    float* h1 = nullptr;  cudaGetSymbolAddress((void**)&h1, g_h1);
    __half *x16, *wt1, *wt2;
    cudaGetSymbolAddress((void**)&x16, g_x16);
    cudaGetSymbolAddress((void**)&wt1, g_wt1);
    cudaGetSymbolAddress((void**)&wt2, g_wt2);

    cudaFuncSetAttribute(conv_mma_kernel,
                         cudaFuncAttributeMaxDynamicSharedMemorySize, SMEM_DYN);

    const int conv_blocks = 2 * ((NPTS + 127) / 128);    // 938 (128x64 tiles)
    const int ew_blocks   = (NPTS * CDIM + 255) / 256;   // 30000
    const int st_blocks   = (NPTS + 511) / 512;          // 118
    const int w_blocks    = (KNBR * CDIM * CDIM + 255) / 256;
    const int mask_words  = (NPTS * KNBR) / 4;           // 405000

    prep_pack_kernel<<<ew_blocks, 256>>>(x);                                   // 0
    prep_w_kernel<<<w_blocks, 256>>>(W1, W2);                                  // 1
    detect_resolve_kernel<<<480, 256>>>((const unsigned*)mask, mask_words);    // 2

    conv_mma_kernel<<<conv_blocks, 256, SMEM_DYN>>>(x16, wt1, nbr, mask, h1);  // 3 (profiled)
    stats_kernel<<<st_blocks, 128>>>(h1, 0);                                   // 4
    finalize_kernel<<<1, 128>>>(g1, b1, 0);                                    // 5
    bn_lrelu_pack_kernel<<<ew_blocks, 256>>>(h1);                              // 6

    conv_mma_kernel<<<conv_blocks, 256, SMEM_DYN>>>(x16, wt2, nbr, mask, out); // 7
    stats_kernel<<<st_blocks, 128>>>(out, 256);                                // 8
    finalize_kernel<<<1, 128>>>(g2, b2, 256);                                  // 9
    bn_res_lrelu_kernel<<<ew_blocks, 256>>>(out, x);                           // 10
}

// round 14
// speedup vs baseline: 10.6633x; 1.0754x over previous
#include <cuda_runtime.h>
#include <cuda_fp16.h>
#include <cstdint>

#define NPTS  60000
#define KNBR  27
#define CDIM  128
#define EPSBN 1e-5f
#define SLOPE 0.01f

// ---------------- device globals (no allocations allowed) ----------------
__device__ __align__(16) __half g_x16[(size_t)NPTS * CDIM];     // fp16 input (x, then y1)
__device__ __align__(16) __half g_wt1[KNBR * CDIM * CDIM];      // W1^T fp16: [k][n][c]
__device__ __align__(16) __half g_wt2[KNBR * CDIM * CDIM];
__device__ float         g_h1[(size_t)NPTS * CDIM];             // conv output scratch
__device__ float         g_sums[512];
__device__ float         g_bn[512];
__device__ unsigned      g_flags;
__device__ unsigned      g_done;
__device__ int           g_mask_mode;

// ---------------- prep: x -> fp16, zero session state ----------------
__global__ void prep_pack_kernel(const float* __restrict__ x) {
    long i = (long)blockIdx.x * blockDim.x + threadIdx.x;
    if (i < (long)NPTS * CDIM) g_x16[i] = __float2half_rn(x[i]);
    if (blockIdx.x == 0) {
        int t = threadIdx.x;                 // blockDim = 256
        g_sums[t]       = 0.f;
        g_sums[t + 256] = 0.f;
        if (t == 0) { g_flags = 0u; g_done = 0u; }
    }
}
__global__ void prep_w_kernel(const float* __restrict__ W1, const float* __restrict__ W2) {
    int i = blockIdx.x * blockDim.x + threadIdx.x;
    if (i < KNBR * CDIM * CDIM) {
        int k = i >> 14, rem = i & 16383, n = rem >> 7, c = rem & 127;
        int src = (k << 14) + (c << 7) + n;
        g_wt1[i] = __float2half_rn(W1[src]);
        g_wt2[i] = __float2half_rn(W2[src]);
    }
}

// ---------------- fused mask-dtype detect + resolve ----------------
__global__ void detect_resolve_kernel(const unsigned* __restrict__ w, int nwords) {
    unsigned f = 0u;
    for (int i = blockIdx.x * blockDim.x + threadIdx.x; i < nwords;
         i += gridDim.x * blockDim.x) {
        unsigned v = w[i];
        if (v == 0x3F800000u)                          f |= 1u;
        else if (v == 0x3F803F80u || v == 0x00003F80u) f |= 2u;
        else if (v > 1u)                               f |= 4u;
    }
    f = __reduce_or_sync(0xFFFFFFFFu, f);
    if ((threadIdx.x & 31) == 0 && f) atomicOr(&g_flags, f);
    __threadfence();
    __syncthreads();
    if (threadIdx.x == 0) {
        unsigned tick = atomicAdd(&g_done, 1u);
        if (tick == gridDim.x - 1) {
            __threadfence();
            unsigned ff = g_flags;
            g_mask_mode = (ff & 2u) ? 3 : (ff & 1u) ? 0 : (ff & 4u) ? 2 : 1;
            g_done = 0u;
        }
    }
}
__device__ __forceinline__ float load_mask(const void* m, long i, int mode) {
    switch (mode) {
        case 0:  return ((const float*)m)[i];
        case 1:  return (float)(((const int*)m)[i] != 0);
        case 2:  return (float)(((const unsigned char*)m)[i] != 0);
        default: return (((const unsigned short*)m)[i] != 0) ? 1.f : 0.f;
    }
}

// ---------------- fp16 mma.sync gather-GEMM, 128x128 CTA tile, 2 CTAs/SM ----------------
// mask bit packed into bit31 of the cached neighbor index (nbr < 2^31).
#define NSTG     3
#define STGB     32768           // per stage: A 16K | B 16K
#define OFF_B    16384
#define OFF_NBR  98304           // 3*32768; 128*27*4 = 13824 bytes of packed nbr|mask
#define SMEM_DYN (112128 + 1024)
#define NSTAGES_TOTAL (2 * KNBR) // 54

__device__ __forceinline__ uint32_t sw128(uint32_t off) { return off ^ ((off >> 3) & 0x70); }
// cp.async with zfill: src_size=0 -> hardware zeros, no global read (R13-validated)
__device__ __forceinline__ void cp16z(uint32_t dst, const void* src, uint32_t ssize) {
    asm volatile("cp.async.cg.shared.global [%0], [%1], 16, %2;"
                 :: "r"(dst), "l"(src), "r"(ssize) : "memory");
}
__device__ __forceinline__ void cp16(uint32_t dst, const void* src) {
    asm volatile("cp.async.cg.shared.global [%0], [%1], 16;" :: "r"(dst), "l"(src) : "memory");
}
#define CP_COMMIT() asm volatile("cp.async.commit_group;" ::: "memory")
#define CP_WAIT2()  asm volatile("cp.async.wait_group 2;" ::: "memory")

__device__ __forceinline__ void ldsm4(uint32_t* r, uint32_t addr) {
    asm volatile("ldmatrix.sync.aligned.m8n8.x4.shared.b16 {%0,%1,%2,%3}, [%4];"
                 : "=r"(r[0]), "=r"(r[1]), "=r"(r[2]), "=r"(r[3]) : "r"(addr));
}
__device__ __forceinline__ void mma16816(float* c, const uint32_t* a, const uint32_t* b) {
    asm volatile(
        "mma.sync.aligned.m16n8k16.row.col.f32.f16.f16.f32 "
        "{%0,%1,%2,%3}, {%4,%5,%6,%7}, {%8,%9}, {%0,%1,%2,%3};"
        : "+f"(c[0]), "+f"(c[1]), "+f"(c[2]), "+f"(c[3])
        : "r"(a[0]), "r"(a[1]), "r"(a[2]), "r"(a[3]), "r"(b[0]), "r"(b[1]));
}

__global__ __launch_bounds__(256, 2)
void conv_mma_kernel(const __half* __restrict__ X16, const __half* __restrict__ Wt,
                     const int* __restrict__ nbr, const void* __restrict__ mask,
                     float* __restrict__ out)
{
    extern __shared__ char smem_raw[];
    uint32_t sb   = (uint32_t)__cvta_generic_to_shared(smem_raw);
    uint32_t base = (sb + 1023) & ~1023u;
    char* smem    = smem_raw + (base - sb);

    unsigned* s_nbr = (unsigned*)(smem + OFF_NBR);   // nb | (mask<<31)

    const int tid = threadIdx.x, lane = tid & 31, wid = tid >> 5;
    const int m0 = blockIdx.x * 128;
    const int mode = g_mask_mode;

    for (int i = tid; i < 128 * KNBR; i += 256) {
        int r = i / KNBR, kk = i - r * KNBR, m = m0 + r;
        unsigned v = 0u;
        if (m < NPTS) {
            long idx = (long)m * KNBR + kk;
            v = (unsigned)nbr[idx];
            if (load_mask(mask, idx, mode) != 0.f) v |= 0x80000000u;
        }
        s_nbr[i] = v;
    }
    __syncthreads();

    float acc[2][8][4];
    #pragma unroll
    for (int mt = 0; mt < 2; ++mt)
        #pragma unroll
        for (int n = 0; n < 8; ++n)
            #pragma unroll
            for (int j = 0; j < 4; ++j) acc[mt][n][j] = 0.f;

    const int wm = (wid & 3) * 32;    // warp M offset (4 warps over 128 rows)
    const int wn = (wid >> 2) * 64;   // warp N offset (2 warps over 128 cols)

    // stage s: neighbor k=s>>1, channels cc=(s&1)*64
    auto load_stage = [&](int s) {
        const int k = s >> 1, cc = (s & 1) << 6;
        const uint32_t stb = base + (uint32_t)(s % NSTG) * STGB;
        // A: 128 rows x 8 chunks = 1024 cp16 (4/thread); masked rows zfill
        #pragma unroll
        for (int j = 0; j < 4; ++j) {
            const int idx = tid * 4 + j;
            const int row = idx >> 3, ch = idx & 7;
            const uint32_t woff = sw128((uint32_t)row * 128 + ch * 16);
            const unsigned v = s_nbr[row * KNBR + k];
            const uint32_t ssize = (v & 0x80000000u) ? 16u : 0u;
            const size_t eoff = (size_t)(v & 0x7FFFFFFFu) * CDIM + cc + ch * 8;
            cp16z(stb + woff, X16 + eoff, ssize);
        }
        // B: 128 rows x 8 chunks = 1024 cp16 (4/thread)
        #pragma unroll
        for (int j = 0; j < 4; ++j) {
            const int idx = tid * 4 + j;
            const int row = idx >> 3, ch = idx & 7;
            const uint32_t woff = sw128((uint32_t)row * 128 + ch * 16);
            const size_t boff = ((size_t)k * CDIM + row) * CDIM + cc + ch * 8;
            cp16(stb + OFF_B + woff, Wt + boff);
        }
    };

    load_stage(0); CP_COMMIT();
    load_stage(1); CP_COMMIT();

    for (int s = 0; s < NSTAGES_TOTAL; ++s) {
        if (s + 2 < NSTAGES_TOTAL) load_stage(s + 2);
        CP_COMMIT();
        CP_WAIT2();                 // stage s arrived (<=2 younger pending)
        __syncthreads();
        const uint32_t stb = base + (uint32_t)(s % NSTG) * STGB;

        #pragma unroll
        for (int kk = 0; kk < 4; ++kk) {
            uint32_t aF[2][4];
            #pragma unroll
            for (int mt = 0; mt < 2; ++mt) {
                const int row  = wm + mt * 16 + (lane & 7) + ((lane >> 3) & 1) * 8;
                const int colb = kk * 32 + ((lane >> 4) & 1) * 16;
                ldsm4(aF[mt], stb + sw128((uint32_t)row * 128 + colb));
            }
            uint32_t bF[8][2];
            #pragma unroll
            for (int nt = 0; nt < 4; ++nt) {
                const int nrow = wn + nt * 16 + ((lane >> 4) & 1) * 8 + (lane & 7);
                const int colb = kk * 32 + ((lane >> 3) & 1) * 16;
                uint32_t t[4];
                ldsm4(t, stb + OFF_B + sw128((uint32_t)nrow * 128 + colb));
                bF[nt*2][0] = t[0]; bF[nt*2][1] = t[1];
                bF[nt*2+1][0] = t[2]; bF[nt*2+1][1] = t[3];
            }
            #pragma unroll
            for (int mt = 0; mt < 2; ++mt)
                #pragma unroll
                for (int n = 0; n < 8; ++n)
                    mma16816(acc[mt][n], aF[mt], bF[n]);
        }
        __syncthreads();           // release buffer (s%NSTG) before reload
    }

    // epilogue: fp32 accumulators -> gmem
    #pragma unroll
    for (int mt = 0; mt < 2; ++mt) {
        const int row = m0 + wm + mt * 16 + (lane >> 2);
        #pragma unroll
        for (int n = 0; n < 8; ++n) {
            const int col = wn + n * 8 + (lane & 3) * 2;
            if (row < NPTS)
                *(float2*)(out + (size_t)row * CDIM + col) = make_float2(acc[mt][n][0], acc[mt][n][1]);
            if (row + 8 < NPTS)
                *(float2*)(out + (size_t)(row + 8) * CDIM + col) = make_float2(acc[mt][n][2], acc[mt][n][3]);
        }
    }
}

// ---------------- BN stats / finalize / fused elementwise ----------------
__global__ void stats_kernel(const float* __restrict__ h, int off) {
    int c    = threadIdx.x;
    int row0 = blockIdx.x * 512;
    int rend = min(row0 + 512, NPTS);
    float s = 0.f, sq = 0.f;
    for (int r = row0; r < rend; ++r) {
        float v = h[(size_t)r * CDIM + c];
        s += v; sq += v * v;
    }
    atomicAdd(&g_sums[off + c], s);
    atomicAdd(&g_sums[off + 128 + c], sq);
}
__global__ void finalize_kernel(const float* __restrict__ gamma,
                                const float* __restrict__ beta, int off) {
    int c = threadIdx.x;
    const float invN = 1.f / (float)NPTS;
    float mean = g_sums[off + c] * invN;
    float var  = g_sums[off + 128 + c] * invN - mean * mean;
    float sc   = gamma[c] / sqrtf(var + EPSBN);
    g_bn[off + c]       = sc;
    g_bn[off + 128 + c] = beta[c] - mean * sc;
}
// y1 = lrelu(bn1(h1)) -> fp16 for conv2
__global__ void bn_lrelu_pack_kernel(const float* __restrict__ h) {
    int i = blockIdx.x * blockDim.x + threadIdx.x;
    if (i < NPTS * CDIM) {
        int c = i & 127;
        float v = fmaf(h[i], g_bn[c], g_bn[128 + c]);
        v = v > 0.f ? v : SLOPE * v;
        g_x16[i] = __float2half_rn(v);
    }
}
// out = lrelu(bn2(h2) + x) in place
__global__ void bn_res_lrelu_kernel(float* __restrict__ h2, const float* __restrict__ x) {
    int i = blockIdx.x * blockDim.x + threadIdx.x;
    if (i < NPTS * CDIM) {
        int c = i & 127;
        float v = fmaf(h2[i], g_bn[256 + c], g_bn[384 + c]) + x[i];
        h2[i] = v > 0.f ? v : SLOPE * v;
    }
}

// ---------------- launch ----------------
extern "C" void kernel_launch(void* const* d_in, const int* in_sizes, int n_in,
                              void* d_out, int out_size)
{
    const float* x    = (const float*)d_in[0];
    const int*   nbr  = (const int*)d_in[1];
    const void*  mask = d_in[2];
    const float* W1   = (const float*)d_in[3];
    const float* W2   = (const float*)d_in[4];
    const float* g1   = (const float*)d_in[5];
    const float* b1   = (const float*)d_in[6];
    const float* g2   = (const float*)d_in[7];
    const float* b2   = (const float*)d_in[8];
    float* out = (float*)d_out;

    float* h1 = nullptr;  cudaGetSymbolAddress((void**)&h1, g_h1);
    __half *x16, *wt1, *wt2;
    cudaGetSymbolAddress((void**)&x16, g_x16);
    cudaGetSymbolAddress((void**)&wt1, g_wt1);
    cudaGetSymbolAddress((void**)&wt2, g_wt2);

    cudaFuncSetAttribute(conv_mma_kernel,
                         cudaFuncAttributeMaxDynamicSharedMemorySize, SMEM_DYN);

    const int conv_blocks = (NPTS + 127) / 128;          // 469 (128x128 tiles)
    const int ew_blocks   = (NPTS * CDIM + 255) / 256;   // 30000
    const int st_blocks   = (NPTS + 511) / 512;          // 118
    const int w_blocks    = (KNBR * CDIM * CDIM + 255) / 256;
    const int mask_words  = (NPTS * KNBR) / 4;           // 405000

    prep_pack_kernel<<<ew_blocks, 256>>>(x);                                   // 0
    prep_w_kernel<<<w_blocks, 256>>>(W1, W2);                                  // 1
    detect_resolve_kernel<<<480, 256>>>((const unsigned*)mask, mask_words);    // 2

    conv_mma_kernel<<<conv_blocks, 256, SMEM_DYN>>>(x16, wt1, nbr, mask, h1);  // 3 (profiled)
    stats_kernel<<<st_blocks, 128>>>(h1, 0);                                   // 4
    finalize_kernel<<<1, 128>>>(g1, b1, 0);                                    // 5
    bn_lrelu_pack_kernel<<<ew_blocks, 256>>>(h1);                              // 6

    conv_mma_kernel<<<conv_blocks, 256, SMEM_DYN>>>(x16, wt2, nbr, mask, out); // 7
    stats_kernel<<<st_blocks, 128>>>(out, 256);                                // 8
    finalize_kernel<<<1, 128>>>(g2, b2, 256);                                  // 9
    bn_res_lrelu_kernel<<<ew_blocks, 256>>>(out, x);                           // 10
}

// round 15
// speedup vs baseline: 11.4829x; 1.0769x over previous
#include <cuda_runtime.h>
#include <cuda_fp16.h>
#include <cstdint>

#define NPTS  60000
#define KNBR  27
#define CDIM  128
#define EPSBN 1e-5f
#define SLOPE 0.01f

// ---------------- device globals (no allocations allowed) ----------------
__device__ __align__(16) __half g_x16[(size_t)NPTS * CDIM];     // fp16 input (x, then y1)
__device__ __align__(16) __half g_wt1[KNBR * CDIM * CDIM];      // W1^T fp16: [k][n][c]
__device__ __align__(16) __half g_wt2[KNBR * CDIM * CDIM];
__device__ float         g_h1[(size_t)NPTS * CDIM];             // conv output scratch
__device__ float         g_sums[512];
__device__ float         g_bn[512];
__device__ unsigned      g_flags;
__device__ unsigned      g_done;
__device__ int           g_mask_mode;

// ---------------- prep: x -> fp16, zero session state ----------------
__global__ void prep_pack_kernel(const float* __restrict__ x) {
    long i = (long)blockIdx.x * blockDim.x + threadIdx.x;
    if (i < (long)NPTS * CDIM) g_x16[i] = __float2half_rn(x[i]);
    if (blockIdx.x == 0) {
        int t = threadIdx.x;                 // blockDim = 256
        g_sums[t]       = 0.f;
        g_sums[t + 256] = 0.f;
        if (t == 0) { g_flags = 0u; g_done = 0u; }
    }
}
__global__ void prep_w_kernel(const float* __restrict__ W1, const float* __restrict__ W2) {
    int i = blockIdx.x * blockDim.x + threadIdx.x;
    if (i < KNBR * CDIM * CDIM) {
        int k = i >> 14, rem = i & 16383, n = rem >> 7, c = rem & 127;
        int src = (k << 14) + (c << 7) + n;
        g_wt1[i] = __float2half_rn(W1[src]);
        g_wt2[i] = __float2half_rn(W2[src]);
    }
}

// ---------------- fused mask-dtype detect + resolve ----------------
__global__ void detect_resolve_kernel(const unsigned* __restrict__ w, int nwords) {
    unsigned f = 0u;
    for (int i = blockIdx.x * blockDim.x + threadIdx.x; i < nwords;
         i += gridDim.x * blockDim.x) {
        unsigned v = w[i];
        if (v == 0x3F800000u)                          f |= 1u;
        else if (v == 0x3F803F80u || v == 0x00003F80u) f |= 2u;
        else if (v > 1u)                               f |= 4u;
    }
    f = __reduce_or_sync(0xFFFFFFFFu, f);
    if ((threadIdx.x & 31) == 0 && f) atomicOr(&g_flags, f);
    __threadfence();
    __syncthreads();
    if (threadIdx.x == 0) {
        unsigned tick = atomicAdd(&g_done, 1u);
        if (tick == gridDim.x - 1) {
            __threadfence();
            unsigned ff = g_flags;
            g_mask_mode = (ff & 2u) ? 3 : (ff & 1u) ? 0 : (ff & 4u) ? 2 : 1;
            g_done = 0u;
        }
    }
}
__device__ __forceinline__ float load_mask(const void* m, long i, int mode) {
    switch (mode) {
        case 0:  return ((const float*)m)[i];
        case 1:  return (float)(((const int*)m)[i] != 0);
        case 2:  return (float)(((const unsigned char*)m)[i] != 0);
        default: return (((const unsigned short*)m)[i] != 0) ? 1.f : 0.f;
    }
}

// ---------------- fp16 mma.sync gather-GEMM, 128x128 CTA tile, 2 CTAs/SM ----------------
// mask bit packed into bit31 of the cached neighbor index (nbr < 2^31).
// BN stats (per-channel sum/sumsq) fused into the epilogue.
#define NSTG     3
#define STGB     32768           // per stage: A 16K | B 16K
#define OFF_B    16384
#define OFF_NBR  98304           // 3*32768; 128*27*4 = 13824 bytes of packed nbr|mask
#define SMEM_DYN (112128 + 1024)
#define NSTAGES_TOTAL (2 * KNBR) // 54

__device__ __forceinline__ uint32_t sw128(uint32_t off) { return off ^ ((off >> 3) & 0x70); }
// cp.async with zfill: src_size=0 -> hardware zeros, no global read (R13-validated)
__device__ __forceinline__ void cp16z(uint32_t dst, const void* src, uint32_t ssize) {
    asm volatile("cp.async.cg.shared.global [%0], [%1], 16, %2;"
                 :: "r"(dst), "l"(src), "r"(ssize) : "memory");
}
__device__ __forceinline__ void cp16(uint32_t dst, const void* src) {
    asm volatile("cp.async.cg.shared.global [%0], [%1], 16;" :: "r"(dst), "l"(src) : "memory");
}
#define CP_COMMIT() asm volatile("cp.async.commit_group;" ::: "memory")
#define CP_WAIT1()  asm volatile("cp.async.wait_group 1;" ::: "memory")
#define CP_WAIT0()  asm volatile("cp.async.wait_group 0;" ::: "memory")

__device__ __forceinline__ void ldsm4(uint32_t* r, uint32_t addr) {
    asm volatile("ldmatrix.sync.aligned.m8n8.x4.shared.b16 {%0,%1,%2,%3}, [%4];"
                 : "=r"(r[0]), "=r"(r[1]), "=r"(r[2]), "=r"(r[3]) : "r"(addr));
}
__device__ __forceinline__ void mma16816(float* c, const uint32_t* a, const uint32_t* b) {
    asm volatile(
        "mma.sync.aligned.m16n8k16.row.col.f32.f16.f16.f32 "
        "{%0,%1,%2,%3}, {%4,%5,%6,%7}, {%8,%9}, {%0,%1,%2,%3};"
        : "+f"(c[0]), "+f"(c[1]), "+f"(c[2]), "+f"(c[3])
        : "r"(a[0]), "r"(a[1]), "r"(a[2]), "r"(a[3]), "r"(b[0]), "r"(b[1]));
}

__global__ __launch_bounds__(256, 2)
void conv_mma_kernel(const __half* __restrict__ X16, const __half* __restrict__ Wt,
                     const int* __restrict__ nbr, const void* __restrict__ mask,
                     float* __restrict__ out, int soff)
{
    extern __shared__ char smem_raw[];
    uint32_t sb   = (uint32_t)__cvta_generic_to_shared(smem_raw);
    uint32_t base = (sb + 1023) & ~1023u;
    char* smem    = smem_raw + (base - sb);

    unsigned* s_nbr = (unsigned*)(smem + OFF_NBR);   // nb | (mask<<31)

    const int tid = threadIdx.x, lane = tid & 31, wid = tid >> 5;
    const int m0 = blockIdx.x * 128;
    const int mode = g_mask_mode;

    for (int i = tid; i < 128 * KNBR; i += 256) {
        int r = i / KNBR, kk = i - r * KNBR, m = m0 + r;
        unsigned v = 0u;
        if (m < NPTS) {
            long idx = (long)m * KNBR + kk;
            v = (unsigned)nbr[idx];
            if (load_mask(mask, idx, mode) != 0.f) v |= 0x80000000u;
        }
        s_nbr[i] = v;
    }
    __syncthreads();

    float acc[2][8][4];
    #pragma unroll
    for (int mt = 0; mt < 2; ++mt)
        #pragma unroll
        for (int n = 0; n < 8; ++n)
            #pragma unroll
            for (int j = 0; j < 4; ++j) acc[mt][n][j] = 0.f;

    const int wm = (wid & 3) * 32;    // warp M offset (4 warps over 128 rows)
    const int wn = (wid >> 2) * 64;   // warp N offset (2 warps over 128 cols)

    // stage s: neighbor k=s>>1, channels cc=(s&1)*64
    auto load_stage = [&](int s) {
        const int k = s >> 1, cc = (s & 1) << 6;
        const uint32_t stb = base + (uint32_t)(s % NSTG) * STGB;
        // A: 128 rows x 8 chunks = 1024 cp16 (4/thread); masked rows zfill
        #pragma unroll
        for (int j = 0; j < 4; ++j) {
            const int idx = tid * 4 + j;
            const int row = idx >> 3, ch = idx & 7;
            const uint32_t woff = sw128((uint32_t)row * 128 + ch * 16);
            const unsigned v = s_nbr[row * KNBR + k];
            const uint32_t ssize = (v & 0x80000000u) ? 16u : 0u;
            const size_t eoff = (size_t)(v & 0x7FFFFFFFu) * CDIM + cc + ch * 8;
            cp16z(stb + woff, X16 + eoff, ssize);
        }
        // B: 128 rows x 8 chunks = 1024 cp16 (4/thread)
        #pragma unroll
        for (int j = 0; j < 4; ++j) {
            const int idx = tid * 4 + j;
            const int row = idx >> 3, ch = idx & 7;
            const uint32_t woff = sw128((uint32_t)row * 128 + ch * 16);
            const size_t boff = ((size_t)k * CDIM + row) * CDIM + cc + ch * 8;
            cp16(stb + OFF_B + woff, Wt + boff);
        }
    };

    load_stage(0); CP_COMMIT();
    load_stage(1); CP_COMMIT();

    // single-sync pipeline: wait(s) -> sync -> load(s+2) -> mma(s)
    for (int s = 0; s < NSTAGES_TOTAL; ++s) {
        if (s < NSTAGES_TOTAL - 1) { CP_WAIT1(); } else { CP_WAIT0(); }
        __syncthreads();            // all warps done with iter s-1 -> buffer (s+2)%3 free
        if (s + 2 < NSTAGES_TOTAL) { load_stage(s + 2); CP_COMMIT(); }
        const uint32_t stb = base + (uint32_t)(s % NSTG) * STGB;

        #pragma unroll
        for (int kk = 0; kk < 4; ++kk) {
            uint32_t aF[2][4];
            #pragma unroll
            for (int mt = 0; mt < 2; ++mt) {
                const int row  = wm + mt * 16 + (lane & 7) + ((lane >> 3) & 1) * 8;
                const int colb = kk * 32 + ((lane >> 4) & 1) * 16;
                ldsm4(aF[mt], stb + sw128((uint32_t)row * 128 + colb));
            }
            uint32_t bF[8][2];
            #pragma unroll
            for (int nt = 0; nt < 4; ++nt) {
                const int nrow = wn + nt * 16 + ((lane >> 4) & 1) * 8 + (lane & 7);
                const int colb = kk * 32 + ((lane >> 3) & 1) * 16;
                uint32_t t[4];
                ldsm4(t, stb + OFF_B + sw128((uint32_t)nrow * 128 + colb));
                bF[nt*2][0] = t[0]; bF[nt*2][1] = t[1];
                bF[nt*2+1][0] = t[2]; bF[nt*2+1][1] = t[3];
            }
            #pragma unroll
            for (int mt = 0; mt < 2; ++mt)
                #pragma unroll
                for (int n = 0; n < 8; ++n)
                    mma16816(acc[mt][n], aF[mt], bF[n]);
        }
    }

    // ---- epilogue: store + fused BN stats ----
    // smem scratch reuses dead stage-buffer memory at base: [c]=sum, [128+c]=sumsq
    float* s_scr = (float*)smem;
    __syncthreads();                 // all warps out of mainloop (no pending smem reads)
    if (tid < 256) s_scr[tid] = 0.f; // 256 floats
    __syncthreads();

    const int rowA0 = m0 + wm + (lane >> 2);        // mt=0 rows: rowA0, rowA0+8
    const int rowB0 = rowA0 + 16;                   // mt=1 rows: rowB0, rowB0+8
    const float gA0 = (rowA0 < NPTS) ? 1.f : 0.f;
    const float gA8 = (rowA0 + 8 < NPTS) ? 1.f : 0.f;
    const float gB0 = (rowB0 < NPTS) ? 1.f : 0.f;
    const float gB8 = (rowB0 + 8 < NPTS) ? 1.f : 0.f;

    #pragma unroll
    for (int n = 0; n < 8; ++n) {
        // column pair c0 = wn + n*8 + (lane&3)*2, c0+1
        float s0 = acc[0][n][0] * gA0 + acc[0][n][2] * gA8
                 + acc[1][n][0] * gB0 + acc[1][n][2] * gB8;
        float s1 = acc[0][n][1] * gA0 + acc[0][n][3] * gA8
                 + acc[1][n][1] * gB0 + acc[1][n][3] * gB8;
        float q0 = acc[0][n][0]*acc[0][n][0]*gA0 + acc[0][n][2]*acc[0][n][2]*gA8
                 + acc[1][n][0]*acc[1][n][0]*gB0 + acc[1][n][2]*acc[1][n][2]*gB8;
        float q1 = acc[0][n][1]*acc[0][n][1]*gA0 + acc[0][n][3]*acc[0][n][3]*gA8
                 + acc[1][n][1]*acc[1][n][1]*gB0 + acc[1][n][3]*acc[1][n][3]*gB8;
        #pragma unroll
        for (int m = 4; m <= 16; m <<= 1) {
            s0 += __shfl_xor_sync(0xFFFFFFFFu, s0, m);
            s1 += __shfl_xor_sync(0xFFFFFFFFu, s1, m);
            q0 += __shfl_xor_sync(0xFFFFFFFFu, q0, m);
            q1 += __shfl_xor_sync(0xFFFFFFFFu, q1, m);
        }
        if (lane < 4) {
            int c0 = wn + n * 8 + lane * 2;
            atomicAdd(&s_scr[c0],           s0);
            atomicAdd(&s_scr[c0 + 1],       s1);
            atomicAdd(&s_scr[128 + c0],     q0);
            atomicAdd(&s_scr[128 + c0 + 1], q1);
        }
    }

    // gmem stores
    #pragma unroll
    for (int mt = 0; mt < 2; ++mt) {
        const int row = m0 + wm + mt * 16 + (lane >> 2);
        #pragma unroll
        for (int n = 0; n < 8; ++n) {
            const int col = wn + n * 8 + (lane & 3) * 2;
            if (row < NPTS)
                *(float2*)(out + (size_t)row * CDIM + col) = make_float2(acc[mt][n][0], acc[mt][n][1]);
            if (row + 8 < NPTS)
                *(float2*)(out + (size_t)(row + 8) * CDIM + col) = make_float2(acc[mt][n][2], acc[mt][n][3]);
        }
    }

    __syncthreads();
    if (tid < 128) {
        atomicAdd(&g_sums[soff + tid],       s_scr[tid]);
        atomicAdd(&g_sums[soff + 128 + tid], s_scr[128 + tid]);
    }
}

// ---------------- BN finalize / fused elementwise ----------------
__global__ void finalize_kernel(const float* __restrict__ gamma,
                                const float* __restrict__ beta, int off) {
    int c = threadIdx.x;
    const float invN = 1.f / (float)NPTS;
    float mean = g_sums[off + c] * invN;
    float var  = g_sums[off + 128 + c] * invN - mean * mean;
    float sc   = gamma[c] / sqrtf(var + EPSBN);
    g_bn[off + c]       = sc;
    g_bn[off + 128 + c] = beta[c] - mean * sc;
}
// y1 = lrelu(bn1(h1)) -> fp16 for conv2
__global__ void bn_lrelu_pack_kernel(const float* __restrict__ h) {
    int i = blockIdx.x * blockDim.x + threadIdx.x;
    if (i < NPTS * CDIM) {
        int c = i & 127;
        float v = fmaf(h[i], g_bn[c], g_bn[128 + c]);
        v = v > 0.f ? v : SLOPE * v;
        g_x16[i] = __float2half_rn(v);
    }
}
// out = lrelu(bn2(h2) + x) in place
__global__ void bn_res_lrelu_kernel(float* __restrict__ h2, const float* __restrict__ x) {
    int i = blockIdx.x * blockDim.x + threadIdx.x;
    if (i < NPTS * CDIM) {
        int c = i & 127;
        float v = fmaf(h2[i], g_bn[256 + c], g_bn[384 + c]) + x[i];
        h2[i] = v > 0.f ? v : SLOPE * v;
    }
}

// ---------------- launch ----------------
extern "C" void kernel_launch(void* const* d_in, const int* in_sizes, int n_in,
                              void* d_out, int out_size)
{
    const float* x    = (const float*)d_in[0];
    const int*   nbr  = (const int*)d_in[1];
    const void*  mask = d_in[2];
    const float* W1   = (const float*)d_in[3];
    const float* W2   = (const float*)d_in[4];
    const float* g1   = (const float*)d_in[5];
    const float* b1   = (const float*)d_in[6];
    const float* g2   = (const float*)d_in[7];
    const float* b2   = (const float*)d_in[8];
    float* out = (float*)d_out;

    float* h1 = nullptr;  cudaGetSymbolAddress((void**)&h1, g_h1);
    __half *x16, *wt1, *wt2;
    cudaGetSymbolAddress((void**)&x16, g_x16);
    cudaGetSymbolAddress((void**)&wt1, g_wt1);
    cudaGetSymbolAddress((void**)&wt2, g_wt2);

    cudaFuncSetAttribute(conv_mma_kernel,
                         cudaFuncAttributeMaxDynamicSharedMemorySize, SMEM_DYN);

    const int conv_blocks = (NPTS + 127) / 128;          // 469 (128x128 tiles)
    const int ew_blocks   = (NPTS * CDIM + 255) / 256;   // 30000
    const int w_blocks    = (KNBR * CDIM * CDIM + 255) / 256;
    const int mask_words  = (NPTS * KNBR) / 4;           // 405000

    prep_pack_kernel<<<ew_blocks, 256>>>(x);                                   // 0
    prep_w_kernel<<<w_blocks, 256>>>(W1, W2);                                  // 1
    detect_resolve_kernel<<<480, 256>>>((const unsigned*)mask, mask_words);    // 2

    conv_mma_kernel<<<conv_blocks, 256, SMEM_DYN>>>(x16, wt1, nbr, mask, h1, 0);   // 3 (profiled)
    finalize_kernel<<<1, 128>>>(g1, b1, 0);                                    // 4
    bn_lrelu_pack_kernel<<<ew_blocks, 256>>>(h1);                              // 5

    conv_mma_kernel<<<conv_blocks, 256, SMEM_DYN>>>(x16, wt2, nbr, mask, out, 256); // 6
    finalize_kernel<<<1, 128>>>(g2, b2, 256);                                  // 7
    bn_res_lrelu_kernel<<<ew_blocks, 256>>>(out, x);                           // 8
}

// round 16
// speedup vs baseline: 11.4842x; 1.0001x over previous
#include <cuda_runtime.h>
#include <cuda_fp16.h>
#include <cstdint>

#define NPTS  60000
#define KNBR  27
#define CDIM  128
#define EPSBN 1e-5f
#define SLOPE 0.01f

// ---------------- device globals (no allocations allowed) ----------------
__device__ __align__(16) __half g_x16[(size_t)NPTS * CDIM];     // fp16 input (x, then y1)
__device__ __align__(16) __half g_wt1[KNBR * CDIM * CDIM];      // W1^T fp16: [k][n][c]
__device__ __align__(16) __half g_wt2[KNBR * CDIM * CDIM];
__device__ float         g_h1[(size_t)NPTS * CDIM];             // conv output scratch
__device__ float         g_sums[512];
__device__ float         g_bn[512];
__device__ unsigned      g_flags;
__device__ unsigned      g_done;
__device__ int           g_mask_mode;

// ---------------- prep: x -> fp16, zero session state ----------------
__global__ void prep_pack_kernel(const float* __restrict__ x) {
    long i = (long)blockIdx.x * blockDim.x + threadIdx.x;
    if (i < (long)NPTS * CDIM) g_x16[i] = __float2half_rn(x[i]);
    if (blockIdx.x == 0) {
        int t = threadIdx.x;                 // blockDim = 256
        g_sums[t]       = 0.f;
        g_sums[t + 256] = 0.f;
        if (t == 0) { g_flags = 0u; g_done = 0u; }
    }
}
__global__ void prep_w_kernel(const float* __restrict__ W1, const float* __restrict__ W2) {
    int i = blockIdx.x * blockDim.x + threadIdx.x;
    if (i < KNBR * CDIM * CDIM) {
        int k = i >> 14, rem = i & 16383, n = rem >> 7, c = rem & 127;
        int src = (k << 14) + (c << 7) + n;
        g_wt1[i] = __float2half_rn(W1[src]);
        g_wt2[i] = __float2half_rn(W2[src]);
    }
}

// ---------------- fused mask-dtype detect + resolve ----------------
__global__ void detect_resolve_kernel(const unsigned* __restrict__ w, int nwords) {
    unsigned f = 0u;
    for (int i = blockIdx.x * blockDim.x + threadIdx.x; i < nwords;
         i += gridDim.x * blockDim.x) {
        unsigned v = w[i];
        if (v == 0x3F800000u)                          f |= 1u;
        else if (v == 0x3F803F80u || v == 0x00003F80u) f |= 2u;
        else if (v > 1u)                               f |= 4u;
    }
    f = __reduce_or_sync(0xFFFFFFFFu, f);
    if ((threadIdx.x & 31) == 0 && f) atomicOr(&g_flags, f);
    __threadfence();
    __syncthreads();
    if (threadIdx.x == 0) {
        unsigned tick = atomicAdd(&g_done, 1u);
        if (tick == gridDim.x - 1) {
            __threadfence();
            unsigned ff = g_flags;
            g_mask_mode = (ff & 2u) ? 3 : (ff & 1u) ? 0 : (ff & 4u) ? 2 : 1;
            g_done = 0u;
        }
    }
}
__device__ __forceinline__ float load_mask(const void* m, long i, int mode) {
    switch (mode) {
        case 0:  return ((const float*)m)[i];
        case 1:  return (float)(((const int*)m)[i] != 0);
        case 2:  return (float)(((const unsigned char*)m)[i] != 0);
        default: return (((const unsigned short*)m)[i] != 0) ? 1.f : 0.f;
    }
}

// ---------------- fp16 mma.sync gather-GEMM, 128x128 CTA tile ----------------
// 512 threads (16 warps of 32x32 tiles), 2 CTAs/SM -> 32 warps/SM.
// mask bit packed into bit31 of the cached neighbor index (nbr < 2^31).
// BN stats fused into the epilogue.
#define NSTG     3
#define STGB     32768           // per stage: A 16K | B 16K
#define OFF_B    16384
#define OFF_NBR  98304           // 3*32768; 128*27*4 = 13824 bytes of packed nbr|mask
#define SMEM_DYN (112128 + 1024)
#define NSTAGES_TOTAL (2 * KNBR) // 54

__device__ __forceinline__ uint32_t sw128(uint32_t off) { return off ^ ((off >> 3) & 0x70); }
__device__ __forceinline__ void cp16z(uint32_t dst, const void* src, uint32_t ssize) {
    asm volatile("cp.async.cg.shared.global [%0], [%1], 16, %2;"
                 :: "r"(dst), "l"(src), "r"(ssize) : "memory");
}
__device__ __forceinline__ void cp16(uint32_t dst, const void* src) {
    asm volatile("cp.async.cg.shared.global [%0], [%1], 16;" :: "r"(dst), "l"(src) : "memory");
}
#define CP_COMMIT() asm volatile("cp.async.commit_group;" ::: "memory")
#define CP_WAIT1()  asm volatile("cp.async.wait_group 1;" ::: "memory")
#define CP_WAIT0()  asm volatile("cp.async.wait_group 0;" ::: "memory")

__device__ __forceinline__ void ldsm4(uint32_t* r, uint32_t addr) {
    asm volatile("ldmatrix.sync.aligned.m8n8.x4.shared.b16 {%0,%1,%2,%3}, [%4];"
                 : "=r"(r[0]), "=r"(r[1]), "=r"(r[2]), "=r"(r[3]) : "r"(addr));
}
__device__ __forceinline__ void mma16816(float* c, const uint32_t* a, const uint32_t* b) {
    asm volatile(
        "mma.sync.aligned.m16n8k16.row.col.f32.f16.f16.f32 "
        "{%0,%1,%2,%3}, {%4,%5,%6,%7}, {%8,%9}, {%0,%1,%2,%3};"
        : "+f"(c[0]), "+f"(c[1]), "+f"(c[2]), "+f"(c[3])
        : "r"(a[0]), "r"(a[1]), "r"(a[2]), "r"(a[3]), "r"(b[0]), "r"(b[1]));
}

__global__ __launch_bounds__(512, 2)
void conv_mma_kernel(const __half* __restrict__ X16, const __half* __restrict__ Wt,
                     const int* __restrict__ nbr, const void* __restrict__ mask,
                     float* __restrict__ out, int soff)
{
    extern __shared__ char smem_raw[];
    uint32_t sb   = (uint32_t)__cvta_generic_to_shared(smem_raw);
    uint32_t base = (sb + 1023) & ~1023u;
    char* smem    = smem_raw + (base - sb);

    unsigned* s_nbr = (unsigned*)(smem + OFF_NBR);   // nb | (mask<<31)

    const int tid = threadIdx.x, lane = tid & 31, wid = tid >> 5;
    const int m0 = blockIdx.x * 128;
    const int mode = g_mask_mode;

    for (int i = tid; i < 128 * KNBR; i += 512) {
        int r = i / KNBR, kk = i - r * KNBR, m = m0 + r;
        unsigned v = 0u;
        if (m < NPTS) {
            long idx = (long)m * KNBR + kk;
            v = (unsigned)nbr[idx];
            if (load_mask(mask, idx, mode) != 0.f) v |= 0x80000000u;
        }
        s_nbr[i] = v;
    }
    __syncthreads();

    float acc[2][4][4];
    #pragma unroll
    for (int mt = 0; mt < 2; ++mt)
        #pragma unroll
        for (int n = 0; n < 4; ++n)
            #pragma unroll
            for (int j = 0; j < 4; ++j) acc[mt][n][j] = 0.f;

    const int wm = (wid & 3) * 32;    // warp M offset (4 row-groups)
    const int wn = (wid >> 2) * 32;   // warp N offset (4 col-groups)

    // stage s: neighbor k=s>>1, channels cc=(s&1)*64
    auto load_stage = [&](int s) {
        const int k = s >> 1, cc = (s & 1) << 6;
        const uint32_t stb = base + (uint32_t)(s % NSTG) * STGB;
        // A: 1024 cp16 (2/thread); masked rows zfill
        #pragma unroll
        for (int j = 0; j < 2; ++j) {
            const int idx = tid * 2 + j;
            const int row = idx >> 3, ch = idx & 7;
            const uint32_t woff = sw128((uint32_t)row * 128 + ch * 16);
            const unsigned v = s_nbr[row * KNBR + k];
            const uint32_t ssize = (v & 0x80000000u) ? 16u : 0u;
            const size_t eoff = (size_t)(v & 0x7FFFFFFFu) * CDIM + cc + ch * 8;
            cp16z(stb + woff, X16 + eoff, ssize);
        }
        // B: 1024 cp16 (2/thread)
        #pragma unroll
        for (int j = 0; j < 2; ++j) {
            const int idx = tid * 2 + j;
            const int row = idx >> 3, ch = idx & 7;
            const uint32_t woff = sw128((uint32_t)row * 128 + ch * 16);
            const size_t boff = ((size_t)k * CDIM + row) * CDIM + cc + ch * 8;
            cp16(stb + OFF_B + woff, Wt + boff);
        }
    };

    load_stage(0); CP_COMMIT();
    load_stage(1); CP_COMMIT();

    // single-sync pipeline: wait(s) -> sync -> load(s+2) -> mma(s)
    for (int s = 0; s < NSTAGES_TOTAL; ++s) {
        if (s < NSTAGES_TOTAL - 1) { CP_WAIT1(); } else { CP_WAIT0(); }
        __syncthreads();            // all warps done with iter s-1 -> buffer (s+2)%3 free
        if (s + 2 < NSTAGES_TOTAL) { load_stage(s + 2); CP_COMMIT(); }
        const uint32_t stb = base + (uint32_t)(s % NSTG) * STGB;

        #pragma unroll
        for (int kk = 0; kk < 4; ++kk) {
            uint32_t aF[2][4];
            #pragma unroll
            for (int mt = 0; mt < 2; ++mt) {
                const int row  = wm + mt * 16 + (lane & 7) + ((lane >> 3) & 1) * 8;
                const int colb = kk * 32 + ((lane >> 4) & 1) * 16;
                ldsm4(aF[mt], stb + sw128((uint32_t)row * 128 + colb));
            }
            uint32_t bF[4][2];
            #pragma unroll
            for (int nt = 0; nt < 2; ++nt) {
                const int nrow = wn + nt * 16 + ((lane >> 4) & 1) * 8 + (lane & 7);
                const int colb = kk * 32 + ((lane >> 3) & 1) * 16;
                uint32_t t[4];
                ldsm4(t, stb + OFF_B + sw128((uint32_t)nrow * 128 + colb));
                bF[nt*2][0] = t[0]; bF[nt*2][1] = t[1];
                bF[nt*2+1][0] = t[2]; bF[nt*2+1][1] = t[3];
            }
            #pragma unroll
            for (int mt = 0; mt < 2; ++mt)
                #pragma unroll
                for (int n = 0; n < 4; ++n)
                    mma16816(acc[mt][n], aF[mt], bF[n]);
        }
    }

    // ---- epilogue: store + fused BN stats ----
    float* s_scr = (float*)smem;     // reuse dead stage-buffer 0
    __syncthreads();
    if (tid < 256) s_scr[tid] = 0.f;
    __syncthreads();

    const int rowA0 = m0 + wm + (lane >> 2);        // mt=0 rows: rowA0, rowA0+8
    const int rowB0 = rowA0 + 16;                   // mt=1 rows: rowB0, rowB0+8
    const float gA0 = (rowA0 < NPTS) ? 1.f : 0.f;
    const float gA8 = (rowA0 + 8 < NPTS) ? 1.f : 0.f;
    const float gB0 = (rowB0 < NPTS) ? 1.f : 0.f;
    const float gB8 = (rowB0 + 8 < NPTS) ? 1.f : 0.f;

    #pragma unroll
    for (int n = 0; n < 4; ++n) {
        float s0 = acc[0][n][0] * gA0 + acc[0][n][2] * gA8
                 + acc[1][n][0] * gB0 + acc[1][n][2] * gB8;
        float s1 = acc[0][n][1] * gA0 + acc[0][n][3] * gA8
                 + acc[1][n][1] * gB0 + acc[1][n][3] * gB8;
        float q0 = acc[0][n][0]*acc[0][n][0]*gA0 + acc[0][n][2]*acc[0][n][2]*gA8
                 + acc[1][n][0]*acc[1][n][0]*gB0 + acc[1][n][2]*acc[1][n][2]*gB8;
        float q1 = acc[0][n][1]*acc[0][n][1]*gA0 + acc[0][n][3]*acc[0][n][3]*gA8
                 + acc[1][n][1]*acc[1][n][1]*gB0 + acc[1][n][3]*acc[1][n][3]*gB8;
        #pragma unroll
        for (int m = 4; m <= 16; m <<= 1) {
            s0 += __shfl_xor_sync(0xFFFFFFFFu, s0, m);
            s1 += __shfl_xor_sync(0xFFFFFFFFu, s1, m);
            q0 += __shfl_xor_sync(0xFFFFFFFFu, q0, m);
            q1 += __shfl_xor_sync(0xFFFFFFFFu, q1, m);
        }
        if (lane < 4) {
            int c0 = wn + n * 8 + lane * 2;
            atomicAdd(&s_scr[c0],           s0);
            atomicAdd(&s_scr[c0 + 1],       s1);
            atomicAdd(&s_scr[128 + c0],     q0);
            atomicAdd(&s_scr[128 + c0 + 1], q1);
        }
    }

    // gmem stores
    #pragma unroll
    for (int mt = 0; mt < 2; ++mt) {
        const int row = m0 + wm + mt * 16 + (lane >> 2);
        #pragma unroll
        for (int n = 0; n < 4; ++n) {
            const int col = wn + n * 8 + (lane & 3) * 2;
            if (row < NPTS)
                *(float2*)(out + (size_t)row * CDIM + col) = make_float2(acc[mt][n][0], acc[mt][n][1]);
            if (row + 8 < NPTS)
                *(float2*)(out + (size_t)(row + 8) * CDIM + col) = make_float2(acc[mt][n][2], acc[mt][n][3]);
        }
    }

    __syncthreads();
    if (tid < 128) {
        atomicAdd(&g_sums[soff + tid],       s_scr[tid]);
        atomicAdd(&g_sums[soff + 128 + tid], s_scr[128 + tid]);
    }
}

// ---------------- BN finalize / fused elementwise ----------------
__global__ void finalize_kernel(const float* __restrict__ gamma,
                                const float* __restrict__ beta, int off) {
    int c = threadIdx.x;
    const float invN = 1.f / (float)NPTS;
    float mean = g_sums[off + c] * invN;
    float var  = g_sums[off + 128 + c] * invN - mean * mean;
    float sc   = gamma[c] / sqrtf(var + EPSBN);
    g_bn[off + c]       = sc;
    g_bn[off + 128 + c] = beta[c] - mean * sc;
}
// y1 = lrelu(bn1(h1)) -> fp16 for conv2
__global__ void bn_lrelu_pack_kernel(const float* __restrict__ h) {
    int i = blockIdx.x * blockDim.x + threadIdx.x;
    if (i < NPTS * CDIM) {
        int c = i & 127;
        float v = fmaf(h[i], g_bn[c], g_bn[128 + c]);
        v = v > 0.f ? v : SLOPE * v;
        g_x16[i] = __float2half_rn(v);
    }
}
// out = lrelu(bn2(h2) + x) in place
__global__ void bn_res_lrelu_kernel(float* __restrict__ h2, const float* __restrict__ x) {
    int i = blockIdx.x * blockDim.x + threadIdx.x;
    if (i < NPTS * CDIM) {
        int c = i & 127;
        float v = fmaf(h2[i], g_bn[256 + c], g_bn[384 + c]) + x[i];
        h2[i] = v > 0.f ? v : SLOPE * v;
    }
}

// ---------------- launch ----------------
extern "C" void kernel_launch(void* const* d_in, const int* in_sizes, int n_in,
                              void* d_out, int out_size)
{
    const float* x    = (const float*)d_in[0];
    const int*   nbr  = (const int*)d_in[1];
    const void*  mask = d_in[2];
    const float* W1   = (const float*)d_in[3];
    const float* W2   = (const float*)d_in[4];
    const float* g1   = (const float*)d_in[5];
    const float* b1   = (const float*)d_in[6];
    const float* g2   = (const float*)d_in[7];
    const float* b2   = (const float*)d_in[8];
    float* out = (float*)d_out;

    float* h1 = nullptr;  cudaGetSymbolAddress((void**)&h1, g_h1);
    __half *x16, *wt1, *wt2;
    cudaGetSymbolAddress((void**)&x16, g_x16);
    cudaGetSymbolAddress((void**)&wt1, g_wt1);
    cudaGetSymbolAddress((void**)&wt2, g_wt2);

    cudaFuncSetAttribute(conv_mma_kernel,
                         cudaFuncAttributeMaxDynamicSharedMemorySize, SMEM_DYN);

    const int conv_blocks = (NPTS + 127) / 128;          // 469 (128x128 tiles)
    const int ew_blocks   = (NPTS * CDIM + 255) / 256;   // 30000
    const int w_blocks    = (KNBR * CDIM * CDIM + 255) / 256;
    const int mask_words  = (NPTS * KNBR) / 4;           // 405000

    prep_pack_kernel<<<ew_blocks, 256>>>(x);                                   // 0
    prep_w_kernel<<<w_blocks, 256>>>(W1, W2);                                  // 1
    detect_resolve_kernel<<<480, 256>>>((const unsigned*)mask, mask_words);    // 2

    conv_mma_kernel<<<conv_blocks, 512, SMEM_DYN>>>(x16, wt1, nbr, mask, h1, 0);   // 3 (profiled)
    finalize_kernel<<<1, 128>>>(g1, b1, 0);                                    // 4
    bn_lrelu_pack_kernel<<<ew_blocks, 256>>>(h1);                              // 5

    conv_mma_kernel<<<conv_blocks, 512, SMEM_DYN>>>(x16, wt2, nbr, mask, out, 256); // 6
    finalize_kernel<<<1, 128>>>(g2, b2, 256);                                  // 7
    bn_res_lrelu_kernel<<<ew_blocks, 256>>>(out, x);                           // 8
}

// round 17
// speedup vs baseline: 12.3040x; 1.0714x over previous
#include <cuda_runtime.h>
#include <cuda_fp16.h>
#include <cstdint>

#define NPTS  60000
#define KNBR  27
#define CDIM  128
#define EPSBN 1e-5f
#define SLOPE 0.01f

// ---------------- device globals (no allocations allowed) ----------------
__device__ __align__(16) __half g_x16[(size_t)NPTS * CDIM];     // fp16 input (x, then y1)
__device__ __align__(16) __half g_wt1[KNBR * CDIM * CDIM];      // W1^T fp16: [k][n][c]
__device__ __align__(16) __half g_wt2[KNBR * CDIM * CDIM];
__device__ float         g_h1[(size_t)NPTS * CDIM];             // conv output scratch
__device__ __align__(16) float g_sums[512];
__device__ __align__(16) float g_bn[512];
__device__ unsigned      g_flags;
__device__ unsigned      g_done;
__device__ int           g_mask_mode;

__device__ __forceinline__ float load_mask(const void* m, long i, int mode) {
    switch (mode) {
        case 0:  return ((const float*)m)[i];
        case 1:  return (float)(((const int*)m)[i] != 0);
        case 2:  return (float)(((const unsigned char*)m)[i] != 0);
        default: return (((const unsigned short*)m)[i] != 0) ? 1.f : 0.f;
    }
}

// ---------------- merged prep: W transpose+fp16, x pack, mask detect+resolve ----------
// block ranges: [0,1728) W;  [1728,9228) x-pack (+ g_sums zero in block 1728);
//               [9228,9484) mask detect (ticket; last block resolves + self-resets)
#define WBLK 1728
#define PBLK 7500
#define DBLK 256
__global__ void prep_all_kernel(const float* __restrict__ x,
                                const float* __restrict__ W1,
                                const float* __restrict__ W2,
                                const unsigned* __restrict__ mw, int nwords)
{
    const int blk = blockIdx.x, tid = threadIdx.x;
    if (blk < WBLK) {
        int i = blk * 256 + tid;                    // 442368 total
        int k = i >> 14, rem = i & 16383, n = rem >> 7, c = rem & 127;
        int src = (k << 14) + (c << 7) + n;
        g_wt1[i] = __float2half_rn(W1[src]);
        g_wt2[i] = __float2half_rn(W2[src]);
        return;
    }
    if (blk < WBLK + PBLK) {
        if (blk == WBLK) {                          // zero session sums (consumed later)
            g_sums[tid]       = 0.f;
            g_sums[tid + 256] = 0.f;
        }
        int i4 = (blk - WBLK) * 256 + tid;          // 1,920,000 float4s
        float4 v = ((const float4*)x)[i4];
        __half2 p0 = __floats2half2_rn(v.x, v.y);
        __half2 p1 = __floats2half2_rn(v.z, v.w);
        uint2 o; o.x = *(unsigned*)&p0; o.y = *(unsigned*)&p1;
        ((uint2*)g_x16)[i4] = o;
        return;
    }
    // ---- mask dtype detect (256 blocks, grid-stride) ----
    {
        unsigned f = 0u;
        const int dblk = blk - WBLK - PBLK;
        for (int i = dblk * 256 + tid; i < nwords; i += DBLK * 256) {
            unsigned v = mw[i];
            if (v == 0x3F800000u)                          f |= 1u;
            else if (v == 0x3F803F80u || v == 0x00003F80u) f |= 2u;
            else if (v > 1u)                               f |= 4u;
        }
        f = __reduce_or_sync(0xFFFFFFFFu, f);
        if ((tid & 31) == 0 && f) atomicOr(&g_flags, f);
        __threadfence();
        __syncthreads();
        if (tid == 0) {
            unsigned tick = atomicAdd(&g_done, 1u);
            if (tick == DBLK - 1) {
                __threadfence();
                unsigned ff = g_flags;
                g_mask_mode = (ff & 2u) ? 3 : (ff & 1u) ? 0 : (ff & 4u) ? 2 : 1;
                g_flags = 0u;   // self-reset for next graph replay
                g_done  = 0u;
            }
        }
    }
}

// ---------------- fp16 mma.sync gather-GEMM, 128x128 CTA tile (R16, ceiling-pinned) ----
#define NSTG     3
#define STGB     32768           // per stage: A 16K | B 16K
#define OFF_B    16384
#define OFF_NBR  98304           // 3*32768; 128*27*4 = 13824 bytes of packed nbr|mask
#define SMEM_DYN (112128 + 1024)
#define NSTAGES_TOTAL (2 * KNBR) // 54

__device__ __forceinline__ uint32_t sw128(uint32_t off) { return off ^ ((off >> 3) & 0x70); }
__device__ __forceinline__ void cp16z(uint32_t dst, const void* src, uint32_t ssize) {
    asm volatile("cp.async.cg.shared.global [%0], [%1], 16, %2;"
                 :: "r"(dst), "l"(src), "r"(ssize) : "memory");
}
__device__ __forceinline__ void cp16(uint32_t dst, const void* src) {
    asm volatile("cp.async.cg.shared.global [%0], [%1], 16;" :: "r"(dst), "l"(src) : "memory");
}
#define CP_COMMIT() asm volatile("cp.async.commit_group;" ::: "memory")
#define CP_WAIT1()  asm volatile("cp.async.wait_group 1;" ::: "memory")
#define CP_WAIT0()  asm volatile("cp.async.wait_group 0;" ::: "memory")

__device__ __forceinline__ void ldsm4(uint32_t* r, uint32_t addr) {
    asm volatile("ldmatrix.sync.aligned.m8n8.x4.shared.b16 {%0,%1,%2,%3}, [%4];"
                 : "=r"(r[0]), "=r"(r[1]), "=r"(r[2]), "=r"(r[3]) : "r"(addr));
}
__device__ __forceinline__ void mma16816(float* c, const uint32_t* a, const uint32_t* b) {
    asm volatile(
        "mma.sync.aligned.m16n8k16.row.col.f32.f16.f16.f32 "
        "{%0,%1,%2,%3}, {%4,%5,%6,%7}, {%8,%9}, {%0,%1,%2,%3};"
        : "+f"(c[0]), "+f"(c[1]), "+f"(c[2]), "+f"(c[3])
        : "r"(a[0]), "r"(a[1]), "r"(a[2]), "r"(a[3]), "r"(b[0]), "r"(b[1]));
}

__global__ __launch_bounds__(512, 2)
void conv_mma_kernel(const __half* __restrict__ X16, const __half* __restrict__ Wt,
                     const int* __restrict__ nbr, const void* __restrict__ mask,
                     float* __restrict__ out, int soff)
{
    extern __shared__ char smem_raw[];
    uint32_t sb   = (uint32_t)__cvta_generic_to_shared(smem_raw);
    uint32_t base = (sb + 1023) & ~1023u;
    char* smem    = smem_raw + (base - sb);

    unsigned* s_nbr = (unsigned*)(smem + OFF_NBR);   // nb | (mask<<31)

    const int tid = threadIdx.x, lane = tid & 31, wid = tid >> 5;
    const int m0 = blockIdx.x * 128;
    const int mode = g_mask_mode;

    for (int i = tid; i < 128 * KNBR; i += 512) {
        int r = i / KNBR, kk = i - r * KNBR, m = m0 + r;
        unsigned v = 0u;
        if (m < NPTS) {
            long idx = (long)m * KNBR + kk;
            v = (unsigned)nbr[idx];
            if (load_mask(mask, idx, mode) != 0.f) v |= 0x80000000u;
        }
        s_nbr[i] = v;
    }
    __syncthreads();

    float acc[2][4][4];
    #pragma unroll
    for (int mt = 0; mt < 2; ++mt)
        #pragma unroll
        for (int n = 0; n < 4; ++n)
            #pragma unroll
            for (int j = 0; j < 4; ++j) acc[mt][n][j] = 0.f;

    const int wm = (wid & 3) * 32;
    const int wn = (wid >> 2) * 32;

    auto load_stage = [&](int s) {
        const int k = s >> 1, cc = (s & 1) << 6;
        const uint32_t stb = base + (uint32_t)(s % NSTG) * STGB;
        #pragma unroll
        for (int j = 0; j < 2; ++j) {
            const int idx = tid * 2 + j;
            const int row = idx >> 3, ch = idx & 7;
            const uint32_t woff = sw128((uint32_t)row * 128 + ch * 16);
            const unsigned v = s_nbr[row * KNBR + k];
            const uint32_t ssize = (v & 0x80000000u) ? 16u : 0u;
            const size_t eoff = (size_t)(v & 0x7FFFFFFFu) * CDIM + cc + ch * 8;
            cp16z(stb + woff, X16 + eoff, ssize);
        }
        #pragma unroll
        for (int j = 0; j < 2; ++j) {
            const int idx = tid * 2 + j;
            const int row = idx >> 3, ch = idx & 7;
            const uint32_t woff = sw128((uint32_t)row * 128 + ch * 16);
            const size_t boff = ((size_t)k * CDIM + row) * CDIM + cc + ch * 8;
            cp16(stb + OFF_B + woff, Wt + boff);
        }
    };

    load_stage(0); CP_COMMIT();
    load_stage(1); CP_COMMIT();

    for (int s = 0; s < NSTAGES_TOTAL; ++s) {
        if (s < NSTAGES_TOTAL - 1) { CP_WAIT1(); } else { CP_WAIT0(); }
        __syncthreads();
        if (s + 2 < NSTAGES_TOTAL) { load_stage(s + 2); CP_COMMIT(); }
        const uint32_t stb = base + (uint32_t)(s % NSTG) * STGB;

        #pragma unroll
        for (int kk = 0; kk < 4; ++kk) {
            uint32_t aF[2][4];
            #pragma unroll
            for (int mt = 0; mt < 2; ++mt) {
                const int row  = wm + mt * 16 + (lane & 7) + ((lane >> 3) & 1) * 8;
                const int colb = kk * 32 + ((lane >> 4) & 1) * 16;
                ldsm4(aF[mt], stb + sw128((uint32_t)row * 128 + colb));
            }
            uint32_t bF[4][2];
            #pragma unroll
            for (int nt = 0; nt < 2; ++nt) {
                const int nrow = wn + nt * 16 + ((lane >> 4) & 1) * 8 + (lane & 7);
                const int colb = kk * 32 + ((lane >> 3) & 1) * 16;
                uint32_t t[4];
                ldsm4(t, stb + OFF_B + sw128((uint32_t)nrow * 128 + colb));
                bF[nt*2][0] = t[0]; bF[nt*2][1] = t[1];
                bF[nt*2+1][0] = t[2]; bF[nt*2+1][1] = t[3];
            }
            #pragma unroll
            for (int mt = 0; mt < 2; ++mt)
                #pragma unroll
                for (int n = 0; n < 4; ++n)
                    mma16816(acc[mt][n], aF[mt], bF[n]);
        }
    }

    // ---- epilogue: store + fused BN stats ----
    float* s_scr = (float*)smem;
    __syncthreads();
    if (tid < 256) s_scr[tid] = 0.f;
    __syncthreads();

    const int rowA0 = m0 + wm + (lane >> 2);
    const int rowB0 = rowA0 + 16;
    const float gA0 = (rowA0 < NPTS) ? 1.f : 0.f;
    const float gA8 = (rowA0 + 8 < NPTS) ? 1.f : 0.f;
    const float gB0 = (rowB0 < NPTS) ? 1.f : 0.f;
    const float gB8 = (rowB0 + 8 < NPTS) ? 1.f : 0.f;

    #pragma unroll
    for (int n = 0; n < 4; ++n) {
        float s0 = acc[0][n][0] * gA0 + acc[0][n][2] * gA8
                 + acc[1][n][0] * gB0 + acc[1][n][2] * gB8;
        float s1 = acc[0][n][1] * gA0 + acc[0][n][3] * gA8
                 + acc[1][n][1] * gB0 + acc[1][n][3] * gB8;
        float q0 = acc[0][n][0]*acc[0][n][0]*gA0 + acc[0][n][2]*acc[0][n][2]*gA8
                 + acc[1][n][0]*acc[1][n][0]*gB0 + acc[1][n][2]*acc[1][n][2]*gB8;
        float q1 = acc[0][n][1]*acc[0][n][1]*gA0 + acc[0][n][3]*acc[0][n][3]*gA8
                 + acc[1][n][1]*acc[1][n][1]*gB0 + acc[1][n][3]*acc[1][n][3]*gB8;
        #pragma unroll
        for (int m = 4; m <= 16; m <<= 1) {
            s0 += __shfl_xor_sync(0xFFFFFFFFu, s0, m);
            s1 += __shfl_xor_sync(0xFFFFFFFFu, s1, m);
            q0 += __shfl_xor_sync(0xFFFFFFFFu, q0, m);
            q1 += __shfl_xor_sync(0xFFFFFFFFu, q1, m);
        }
        if (lane < 4) {
            int c0 = wn + n * 8 + lane * 2;
            atomicAdd(&s_scr[c0],           s0);
            atomicAdd(&s_scr[c0 + 1],       s1);
            atomicAdd(&s_scr[128 + c0],     q0);
            atomicAdd(&s_scr[128 + c0 + 1], q1);
        }
    }

    #pragma unroll
    for (int mt = 0; mt < 2; ++mt) {
        const int row = m0 + wm + mt * 16 + (lane >> 2);
        #pragma unroll
        for (int n = 0; n < 4; ++n) {
            const int col = wn + n * 8 + (lane & 3) * 2;
            if (row < NPTS)
                *(float2*)(out + (size_t)row * CDIM + col) = make_float2(acc[mt][n][0], acc[mt][n][1]);
            if (row + 8 < NPTS)
                *(float2*)(out + (size_t)(row + 8) * CDIM + col) = make_float2(acc[mt][n][2], acc[mt][n][3]);
        }
    }

    __syncthreads();
    if (tid < 128) {
        atomicAdd(&g_sums[soff + tid],       s_scr[tid]);
        atomicAdd(&g_sums[soff + 128 + tid], s_scr[128 + tid]);
    }
}

// ---------------- BN finalize / vectorized fused elementwise ----------------
__global__ void finalize_kernel(const float* __restrict__ gamma,
                                const float* __restrict__ beta, int off) {
    int c = threadIdx.x;
    const float invN = 1.f / (float)NPTS;
    float mean = g_sums[off + c] * invN;
    float var  = g_sums[off + 128 + c] * invN - mean * mean;
    float sc   = gamma[c] / sqrtf(var + EPSBN);
    g_bn[off + c]       = sc;
    g_bn[off + 128 + c] = beta[c] - mean * sc;
}
// y1 = lrelu(bn1(h1)) -> fp16 for conv2 (float4 vectorized; 3750 x 512 exact)
__global__ void bn_lrelu_pack_kernel(const float* __restrict__ h) {
    int i4 = blockIdx.x * 512 + threadIdx.x;
    float4 v = ((const float4*)h)[i4];
    int c4 = i4 & 31;
    float4 sc = ((const float4*)g_bn)[c4];
    float4 sh = ((const float4*)(g_bn + 128))[c4];
    float o0 = fmaf(v.x, sc.x, sh.x); o0 = o0 > 0.f ? o0 : SLOPE * o0;
    float o1 = fmaf(v.y, sc.y, sh.y); o1 = o1 > 0.f ? o1 : SLOPE * o1;
    float o2 = fmaf(v.z, sc.z, sh.z); o2 = o2 > 0.f ? o2 : SLOPE * o2;
    float o3 = fmaf(v.w, sc.w, sh.w); o3 = o3 > 0.f ? o3 : SLOPE * o3;
    __half2 p0 = __floats2half2_rn(o0, o1);
    __half2 p1 = __floats2half2_rn(o2, o3);
    uint2 o; o.x = *(unsigned*)&p0; o.y = *(unsigned*)&p1;
    ((uint2*)g_x16)[i4] = o;
}
// out = lrelu(bn2(h2) + x) in place (float4 vectorized)
__global__ void bn_res_lrelu_kernel(float* __restrict__ h2, const float* __restrict__ x) {
    int i4 = blockIdx.x * 512 + threadIdx.x;
    float4 v = ((const float4*)h2)[i4];
    float4 xv = ((const float4*)x)[i4];
    int c4 = i4 & 31;
    float4 sc = ((const float4*)(g_bn + 256))[c4];
    float4 sh = ((const float4*)(g_bn + 384))[c4];
    float o0 = fmaf(v.x, sc.x, sh.x) + xv.x; o0 = o0 > 0.f ? o0 : SLOPE * o0;
    float o1 = fmaf(v.y, sc.y, sh.y) + xv.y; o1 = o1 > 0.f ? o1 : SLOPE * o1;
    float o2 = fmaf(v.z, sc.z, sh.z) + xv.z; o2 = o2 > 0.f ? o2 : SLOPE * o2;
    float o3 = fmaf(v.w, sc.w, sh.w) + xv.w; o3 = o3 > 0.f ? o3 : SLOPE * o3;
    ((float4*)h2)[i4] = make_float4(o0, o1, o2, o3);
}

// ---------------- launch ----------------
extern "C" void kernel_launch(void* const* d_in, const int* in_sizes, int n_in,
                              void* d_out, int out_size)
{
    const float* x    = (const float*)d_in[0];
    const int*   nbr  = (const int*)d_in[1];
    const void*  mask = d_in[2];
    const float* W1   = (const float*)d_in[3];
    const float* W2   = (const float*)d_in[4];
    const float* g1   = (const float*)d_in[5];
    const float* b1   = (const float*)d_in[6];
    const float* g2   = (const float*)d_in[7];
    const float* b2   = (const float*)d_in[8];
    float* out = (float*)d_out;

    float* h1 = nullptr;  cudaGetSymbolAddress((void**)&h1, g_h1);
    __half *x16, *wt1, *wt2;
    cudaGetSymbolAddress((void**)&x16, g_x16);
    cudaGetSymbolAddress((void**)&wt1, g_wt1);
    cudaGetSymbolAddress((void**)&wt2, g_wt2);

    cudaFuncSetAttribute(conv_mma_kernel,
                         cudaFuncAttributeMaxDynamicSharedMemorySize, SMEM_DYN);

    const int conv_blocks = (NPTS + 127) / 128;          // 469
    const int ew4_blocks  = (NPTS * CDIM / 4 + 511) / 512; // 3750 exact
    const int mask_words  = (NPTS * KNBR) / 4;           // 405000

    prep_all_kernel<<<WBLK + PBLK + DBLK, 256>>>(x, W1, W2, (const unsigned*)mask, mask_words); // 0

    conv_mma_kernel<<<conv_blocks, 512, SMEM_DYN>>>(x16, wt1, nbr, mask, h1, 0);    // 1
    finalize_kernel<<<1, 128>>>(g1, b1, 0);                                         // 2
    bn_lrelu_pack_kernel<<<ew4_blocks, 512>>>(h1);                                  // 3 (profiled)

    conv_mma_kernel<<<conv_blocks, 512, SMEM_DYN>>>(x16, wt2, nbr, mask, out, 256); // 4
    finalize_kernel<<<1, 128>>>(g2, b2, 256);                                       // 5
    bn_res_lrelu_kernel<<<ew4_blocks, 512>>>(out, x);                               // 6
}